// round 5
// baseline (speedup 1.0000x reference)
#include <cuda_runtime.h>
#include <cuda_bf16.h>
#include <math.h>
#include <stdint.h>

#define D_MODEL 2048
#define N_HEADS 16
#define HEAD_DIM 128
#define MLP_DIM 8192
#define BATCH 2
#define SEQ 2048
#define TOK (BATCH * SEQ)

typedef __nv_bfloat16 bf16;

// ---------------- scratch (static device globals) ---------------------------
__device__ bf16 g_h_hi[(size_t)TOK * D_MODEL],  g_h_lo[(size_t)TOK * D_MODEL];
__device__ bf16 g_q_hi[(size_t)TOK * D_MODEL],  g_q_lo[(size_t)TOK * D_MODEL];
__device__ bf16 g_k_hi[(size_t)TOK * D_MODEL],  g_k_lo[(size_t)TOK * D_MODEL];
__device__ bf16 g_v_hi[(size_t)TOK * D_MODEL],  g_v_lo[(size_t)TOK * D_MODEL];
__device__ bf16 g_att_hi[(size_t)TOK * D_MODEL], g_att_lo[(size_t)TOK * D_MODEL];
__device__ bf16 g_up_hi[(size_t)TOK * MLP_DIM], g_up_lo[(size_t)TOK * MLP_DIM];
__device__ bf16 g_wq_hi[(size_t)D_MODEL * D_MODEL], g_wq_lo[(size_t)D_MODEL * D_MODEL];
__device__ bf16 g_wk_hi[(size_t)D_MODEL * D_MODEL], g_wk_lo[(size_t)D_MODEL * D_MODEL];
__device__ bf16 g_wv_hi[(size_t)D_MODEL * D_MODEL], g_wv_lo[(size_t)D_MODEL * D_MODEL];
__device__ bf16 g_wo_hi[(size_t)D_MODEL * D_MODEL], g_wo_lo[(size_t)D_MODEL * D_MODEL];
__device__ bf16 g_wu_hi[(size_t)MLP_DIM * D_MODEL], g_wu_lo[(size_t)MLP_DIM * D_MODEL];
__device__ bf16 g_wd_hi[(size_t)D_MODEL * MLP_DIM], g_wd_lo[(size_t)D_MODEL * MLP_DIM];
__device__ float g_x1[(size_t)TOK * D_MODEL];

// ================= PTX helpers (baseline PTX, sm_80+) =======================
__device__ __forceinline__ uint32_t smem_to_u32(const void* p) {
    uint32_t a;
    asm("{ .reg .u64 t; cvta.to.shared.u64 t, %1; cvt.u32.u64 %0, t; }"
        : "=r"(a) : "l"(p));
    return a;
}
__device__ __forceinline__ void ldsm_x4(uint32_t addr, uint32_t* r) {
    asm volatile("ldmatrix.sync.aligned.m8n8.x4.shared.b16 {%0,%1,%2,%3}, [%4];"
                 : "=r"(r[0]), "=r"(r[1]), "=r"(r[2]), "=r"(r[3]) : "r"(addr));
}
__device__ __forceinline__ void mma_bf16(float* d, const uint32_t* a,
                                         const uint32_t* b) {
    asm volatile(
        "mma.sync.aligned.m16n8k16.row.col.f32.bf16.bf16.f32 "
        "{%0,%1,%2,%3}, {%4,%5,%6,%7}, {%8,%9}, {%0,%1,%2,%3};"
        : "+f"(d[0]), "+f"(d[1]), "+f"(d[2]), "+f"(d[3])
        : "r"(a[0]), "r"(a[1]), "r"(a[2]), "r"(a[3]), "r"(b[0]), "r"(b[1]));
}
__device__ __forceinline__ uint32_t bf2_bits(__nv_bfloat162 v) {
    return *reinterpret_cast<uint32_t*>(&v);
}
#define CP16(dst, src) \
    asm volatile("cp.async.cg.shared.global [%0], [%1], 16;" \
                 :: "r"(dst), "l"(src) : "memory")
#define CPCOMMIT() asm volatile("cp.async.commit_group;" ::: "memory")
#define CPWAIT(n)  asm volatile("cp.async.wait_group %0;" :: "n"(n) : "memory")

// ================= fp32 -> bf16 hi/lo split (weights) ========================
__global__ void split_fp32(const float* __restrict__ src,
                           bf16* __restrict__ hi, bf16* __restrict__ lo, int n4) {
    int i = blockIdx.x * blockDim.x + threadIdx.x;
    if (i >= n4) return;
    float4 v = reinterpret_cast<const float4*>(src)[i];
    __nv_bfloat162 h01 = __floats2bfloat162_rn(v.x, v.y);
    __nv_bfloat162 h23 = __floats2bfloat162_rn(v.z, v.w);
    __nv_bfloat162 l01 = __floats2bfloat162_rn(v.x - __bfloat162float(h01.x),
                                               v.y - __bfloat162float(h01.y));
    __nv_bfloat162 l23 = __floats2bfloat162_rn(v.z - __bfloat162float(h23.x),
                                               v.w - __bfloat162float(h23.y));
    reinterpret_cast<uint2*>(hi)[i] = make_uint2(bf2_bits(h01), bf2_bits(h23));
    reinterpret_cast<uint2*>(lo)[i] = make_uint2(bf2_bits(l01), bf2_bits(l23));
}

// ================= RMSNorm -> bf16 hi/lo =====================================
__global__ void rmsnorm_split(const float* __restrict__ x,
                              const float* __restrict__ w,
                              bf16* __restrict__ hi, bf16* __restrict__ lo) {
    int row = blockIdx.x;
    const float4* xr = reinterpret_cast<const float4*>(x + (size_t)row * D_MODEL);
    const float4* w4 = reinterpret_cast<const float4*>(w);

    float ss = 0.f;
    for (int i = threadIdx.x; i < D_MODEL / 4; i += blockDim.x) {
        float4 v = xr[i];
        ss += v.x * v.x + v.y * v.y + v.z * v.z + v.w * v.w;
    }
    for (int off = 16; off > 0; off >>= 1)
        ss += __shfl_xor_sync(0xFFFFFFFFu, ss, off);
    __shared__ float red[8];
    __shared__ float s_rms;
    int lane = threadIdx.x & 31, wid = threadIdx.x >> 5;
    if (lane == 0) red[wid] = ss;
    __syncthreads();
    if (threadIdx.x == 0) {
        float tt = 0.f;
        #pragma unroll
        for (int i = 0; i < 8; i++) tt += red[i];
        s_rms = rsqrtf(tt / (float)D_MODEL + 1e-6f);
    }
    __syncthreads();
    float r = s_rms;
    uint2* h2 = reinterpret_cast<uint2*>(hi + (size_t)row * D_MODEL);
    uint2* l2 = reinterpret_cast<uint2*>(lo + (size_t)row * D_MODEL);
    for (int i = threadIdx.x; i < D_MODEL / 4; i += blockDim.x) {
        float4 v = xr[i];
        float4 ww = w4[i];
        float y0 = v.x * r * ww.x, y1 = v.y * r * ww.y;
        float y2 = v.z * r * ww.z, y3 = v.w * r * ww.w;
        __nv_bfloat162 h01 = __floats2bfloat162_rn(y0, y1);
        __nv_bfloat162 h23 = __floats2bfloat162_rn(y2, y3);
        __nv_bfloat162 l01 = __floats2bfloat162_rn(y0 - __bfloat162float(h01.x),
                                                   y1 - __bfloat162float(h01.y));
        __nv_bfloat162 l23 = __floats2bfloat162_rn(y2 - __bfloat162float(h23.x),
                                                   y3 - __bfloat162float(h23.y));
        h2[i] = make_uint2(bf2_bits(h01), bf2_bits(h23));
        l2[i] = make_uint2(bf2_bits(l01), bf2_bits(l23));
    }
}

// ================= bf16-split GEMM via mma.sync + cp.async ===================
// C = A @ B^T with A = Ah+Al, B = Bh+Bl; acc += Ah*Bh + Ah*Bl + Al*Bh.
// EPI: 0 = split-store bf16 hi/lo, 1 = gelu + split-store, 2 = residual fp32
#define KC 32
#define ROWB 128
#define TILE_B (128 * ROWB)       // 16 KB
#define STAGE_B (2 * TILE_B)      // 32 KB (A+B)
#define NSTAGE 4
#define GEMM_SMEM (NSTAGE * STAGE_B)  // 128 KB

template <int EPI>
__global__ void __launch_bounds__(256)
mma_gemm(int M, int N, int K,
         const bf16* __restrict__ Ah_, const bf16* __restrict__ Al_,
         const bf16* __restrict__ Bh_, const bf16* __restrict__ Bl_,
         const float* __restrict__ RES, float* __restrict__ Cf,
         bf16* __restrict__ Ch, bf16* __restrict__ Cl) {
    extern __shared__ char smem[];
    const uint32_t su = smem_to_u32(smem);

    const int t = threadIdx.x;
    const int lane = t & 31;
    const int wid = t >> 5;
    const int wm = wid & 3;
    const int wn = wid >> 2;
    const int m0 = blockIdx.y * 128;
    const int n0 = blockIdx.x * 128;

    const int lrow = t >> 1;
    const int half = t & 1;
    const bf16* Asrc = (half ? Al_ : Ah_) + (size_t)(m0 + lrow) * K;
    const bf16* Bsrc = (half ? Bl_ : Bh_) + (size_t)(n0 + lrow) * K;
    const uint32_t sw = (uint32_t)(lrow & 7) << 4;
    const uint32_t drow = (uint32_t)lrow * ROWB;

    auto CP_chunk = [&](int s, int k0) {
        const uint32_t stA = su + (uint32_t)s * STAGE_B;
        const uint32_t stB = stA + TILE_B;
        #pragma unroll
        for (int c = 0; c < 4; c++) {
            const uint32_t d = drow + (((uint32_t)(half * 64 + c * 16)) ^ sw);
            CP16(stA + d, Asrc + k0 + c * 8);
            CP16(stB + d, Bsrc + k0 + c * 8);
        }
    };

    float acc[2][8][4];
    #pragma unroll
    for (int mt = 0; mt < 2; mt++)
        #pragma unroll
        for (int nt = 0; nt < 8; nt++)
            #pragma unroll
            for (int j = 0; j < 4; j++) acc[mt][nt][j] = 0.f;

    const int nch = K / KC;
    #pragma unroll
    for (int s = 0; s < NSTAGE - 1; s++) {
        if (s < nch) { CP_chunk(s, s * KC); }
        CPCOMMIT();
    }

    const int lrow16 = lane & 15;
    const int cg = (lane >> 4) & 1;

    for (int i = 0; i < nch; i++) {
        CPWAIT(NSTAGE - 2);
        __syncthreads();

        const uint32_t sA = su + (uint32_t)(i % NSTAGE) * STAGE_B;
        const uint32_t sB = sA + TILE_B;

        #pragma unroll
        for (int ks = 0; ks < 2; ks++) {
            const uint32_t cbh = (uint32_t)(ks * 32 + cg * 16);
            uint32_t Ahf[2][4], Alf[2][4];
            #pragma unroll
            for (int mt = 0; mt < 2; mt++) {
                const int row = wm * 32 + mt * 16 + lrow16;
                const uint32_t swz = (uint32_t)(row & 7) << 4;
                const uint32_t base = sA + (uint32_t)row * ROWB;
                ldsm_x4(base + (cbh ^ swz), Ahf[mt]);
                ldsm_x4(base + ((cbh + 64) ^ swz), Alf[mt]);
            }
            #pragma unroll
            for (int q = 0; q < 4; q++) {
                const int row = wn * 64 + q * 16 + lrow16;
                const uint32_t swz = (uint32_t)(row & 7) << 4;
                const uint32_t base = sB + (uint32_t)row * ROWB;
                uint32_t rh[4], rl[4];
                ldsm_x4(base + (cbh ^ swz), rh);
                ldsm_x4(base + ((cbh + 64) ^ swz), rl);
                uint32_t bh0[2] = {rh[0], rh[2]};
                uint32_t bh1[2] = {rh[1], rh[3]};
                uint32_t bl0[2] = {rl[0], rl[2]};
                uint32_t bl1[2] = {rl[1], rl[3]};
                #pragma unroll
                for (int mt = 0; mt < 2; mt++) {
                    mma_bf16(acc[mt][2 * q + 0], Ahf[mt], bh0);
                    mma_bf16(acc[mt][2 * q + 0], Ahf[mt], bl0);
                    mma_bf16(acc[mt][2 * q + 0], Alf[mt], bh0);
                    mma_bf16(acc[mt][2 * q + 1], Ahf[mt], bh1);
                    mma_bf16(acc[mt][2 * q + 1], Ahf[mt], bl1);
                    mma_bf16(acc[mt][2 * q + 1], Alf[mt], bh1);
                }
            }
        }

        if (i + NSTAGE - 1 < nch) {
            CP_chunk((i + NSTAGE - 1) % NSTAGE, (i + NSTAGE - 1) * KC);
            CPCOMMIT();
        }
    }

    // ---- epilogue ----
    const int er0 = m0 + wm * 32 + (lane >> 2);
    const int ec0 = n0 + wn * 64 + (lane & 3) * 2;
    #pragma unroll
    for (int mt = 0; mt < 2; mt++) {
        #pragma unroll
        for (int g = 0; g < 2; g++) {
            const int row = er0 + mt * 16 + g * 8;
            #pragma unroll
            for (int nt = 0; nt < 8; nt++) {
                const int col = ec0 + nt * 8;
                float v0 = acc[mt][nt][g * 2 + 0];
                float v1 = acc[mt][nt][g * 2 + 1];
                size_t roff = (size_t)row * N + col;
                if (EPI == 2) {
                    float2 r = *reinterpret_cast<const float2*>(RES + roff);
                    *reinterpret_cast<float2*>(Cf + roff) =
                        make_float2(v0 + r.x, v1 + r.y);
                } else {
                    if (EPI == 1) {
                        v0 = 0.5f * v0 * (1.0f + erff(v0 * 0.70710678118654752f));
                        v1 = 0.5f * v1 * (1.0f + erff(v1 * 0.70710678118654752f));
                    }
                    __nv_bfloat162 hh = __floats2bfloat162_rn(v0, v1);
                    __nv_bfloat162 ll = __floats2bfloat162_rn(
                        v0 - __bfloat162float(hh.x), v1 - __bfloat162float(hh.y));
                    *reinterpret_cast<uint32_t*>(Ch + roff) = bf2_bits(hh);
                    *reinterpret_cast<uint32_t*>(Cl + roff) = bf2_bits(ll);
                }
            }
        }
    }
}

// ================= tensor-core flash attention (bf16 split inputs) ===========
// smem: buf1/Q [0,64K), buf0 [64K,128K), mask [128K,+512)
// buffer sublayout: K hi [0,16K) lo [16K,32K) | Vt hi [32K,48K) lo [48K,64K)
// Q staging (pre-loop): hi [0,32K), lo [32K,64K)
#define ATT_BUF0 65536
#define ATT_MASK 131072
#define ATT_SMEM_BYTES (131072 + 512)

__device__ __forceinline__ void att_stage_chunk(
    char* smem, uint32_t sb, uint32_t bufoff,
    const bf16* __restrict__ Kh, const bf16* __restrict__ Kl,
    const bf16* __restrict__ Vh, const bf16* __restrict__ Vl,
    const int* __restrict__ bm, int kv0, int slot, int t) {
    // K tile via cp.async: row = t>>2 (0..63), dq = (t&3)*32 d-values
    {
        const int row = t >> 2;
        const int dq = (t & 3) * 32;
        const size_t goff = (size_t)(kv0 + row) * D_MODEL + dq;
        const uint32_t rbase = sb + bufoff + (uint32_t)row * 256;
        const uint32_t swr = (uint32_t)(row & 7) << 4;
        #pragma unroll
        for (int i = 0; i < 4; i++) {
            const uint32_t off = ((uint32_t)(dq * 2 + i * 16)) ^ swr;
            CP16(rbase + off, Kh + goff + i * 8);
            CP16(rbase + 16384 + off, Kl + goff + i * 8);
        }
    }
    // Vt tile: transpose V[kv][d] -> Vt[d][kv] via byte_perm repack
    {
        const int kvp = t & 31;     // kv pair index
        const int dblk = t >> 5;    // 16 d-values per thread
        const size_t r0 = (size_t)(kv0 + 2 * kvp) * D_MODEL + dblk * 16;
        const size_t r1 = r0 + D_MODEL;
        const uint32_t* h0 = reinterpret_cast<const uint32_t*>(Vh + r0);
        const uint32_t* h1 = reinterpret_cast<const uint32_t*>(Vh + r1);
        const uint32_t* l0 = reinterpret_cast<const uint32_t*>(Vl + r0);
        const uint32_t* l1 = reinterpret_cast<const uint32_t*>(Vl + r1);
        const uint32_t koff = (uint32_t)(kvp * 4);
        #pragma unroll
        for (int dd = 0; dd < 8; dd++) {
            const int d0 = dblk * 16 + dd * 2;
            uint32_t a = h0[dd], b = h1[dd];
            uint32_t c = l0[dd], e = l1[dd];
            const uint32_t vb0 = sb + bufoff + 32768 + (uint32_t)d0 * 128 +
                                 (koff ^ ((uint32_t)(d0 & 7) << 4));
            const uint32_t vb1 = sb + bufoff + 32768 + (uint32_t)(d0 + 1) * 128 +
                                 (koff ^ ((uint32_t)((d0 + 1) & 7) << 4));
            asm volatile("st.shared.b32 [%0], %1;" :: "r"(vb0),
                         "r"(__byte_perm(a, b, 0x5410)) : "memory");
            asm volatile("st.shared.b32 [%0], %1;" :: "r"(vb1),
                         "r"(__byte_perm(a, b, 0x7632)) : "memory");
            asm volatile("st.shared.b32 [%0], %1;" :: "r"(vb0 + 16384),
                         "r"(__byte_perm(c, e, 0x5410)) : "memory");
            asm volatile("st.shared.b32 [%0], %1;" :: "r"(vb1 + 16384),
                         "r"(__byte_perm(c, e, 0x7632)) : "memory");
        }
    }
    if (t < 64)
        reinterpret_cast<int*>(smem + ATT_MASK + slot * 256)[t] = bm[kv0 + t];
}

__global__ void __launch_bounds__(256, 1)
flash_attn_tc(const bf16* __restrict__ Qh, const bf16* __restrict__ Ql,
              const bf16* __restrict__ Kh, const bf16* __restrict__ Kl,
              const bf16* __restrict__ Vh, const bf16* __restrict__ Vl,
              const int* __restrict__ mask,
              bf16* __restrict__ Oh, bf16* __restrict__ Ol) {
    extern __shared__ char smem[];
    const uint32_t sb = smem_to_u32(smem);
    const int t = threadIdx.x, lane = t & 31, w = t >> 5;
    const int qi = gridDim.x - 1 - blockIdx.x;  // longest-work CTAs first
    const int h = blockIdx.y, b = blockIdx.z;
    const int q0 = qi * 128;
    const size_t base = (size_t)b * SEQ * D_MODEL + (size_t)h * HEAD_DIM;
    const int* bm = mask + b * SEQ;
    const float scale = 0.08838834764831845f;  // 1/sqrt(128)

    // ---- stage Q (plain copies from bf16 hi/lo) ----
    {
        const int row = t >> 1, half = t & 1;
        const size_t goff = base + (size_t)(q0 + row) * D_MODEL + half * 64;
        const uint4* ghv = reinterpret_cast<const uint4*>(Qh + goff);
        const uint4* glv = reinterpret_cast<const uint4*>(Ql + goff);
        char* qr = smem + (uint32_t)row * 256;
        const uint32_t swr = (uint32_t)(row & 7) << 4;
        #pragma unroll
        for (int i = 0; i < 8; i++) {
            const uint32_t off = ((uint32_t)(half * 128 + i * 16)) ^ swr;
            *reinterpret_cast<uint4*>(qr + off) = ghv[i];
            *reinterpret_cast<uint4*>(qr + 32768 + off) = glv[i];
        }
    }
    att_stage_chunk(smem, sb, ATT_BUF0, Kh + base, Kl + base,
                    Vh + base, Vl + base, bm, 0, 0, t);
    CPCOMMIT();
    CPWAIT(0);
    __syncthreads();

    // ---- preload Q fragments (constant across KV chunks) ----
    uint32_t Aqh[8][4], Aql[8][4];
    {
        const int r = w * 16 + (lane & 15);
        const uint32_t swz = (uint32_t)(r & 7) << 4;
        const uint32_t cgo = ((uint32_t)(lane >> 4)) << 4;
        const uint32_t qb = sb + (uint32_t)r * 256;
        #pragma unroll
        for (int ds = 0; ds < 8; ds++) {
            const uint32_t off = (((uint32_t)(ds * 32)) + cgo) ^ swz;
            ldsm_x4(qb + off, Aqh[ds]);
            ldsm_x4(qb + 32768 + off, Aql[ds]);
        }
    }
    __syncthreads();  // Q frags read before chunk-1 staging may overwrite

    float m1 = -1e30f, l1 = 0.f, m2 = -1e30f, l2 = 0.f;
    float acc[16][4];
    #pragma unroll
    for (int nt = 0; nt < 16; nt++)
        #pragma unroll
        for (int c = 0; c < 4; c++) acc[nt][c] = 0.f;

    const int r1g = q0 + w * 16 + (lane >> 2);
    const int r2g = r1g + 8;
    const int nch = 2 * qi + 2;
    const uint32_t cgo = ((uint32_t)(lane >> 4)) << 4;

    for (int j = 0; j < nch; j++) {
        const int s = j & 1;
        const uint32_t bufo = s ? 0u : (uint32_t)ATT_BUF0;
        const int kv0 = j * 64;

        // stage chunk j+1 into the other buffer (overlaps with compute below)
        if (j + 1 < nch) {
            att_stage_chunk(smem, sb, s ? (uint32_t)ATT_BUF0 : 0u,
                            Kh + base, Kl + base, Vh + base, Vl + base,
                            bm, kv0 + 64, (j + 1) & 1, t);
            CPCOMMIT();
        }

        // ---- scores S = Q K^T (3-pass split) ----
        float sacc[8][4];
        #pragma unroll
        for (int nt = 0; nt < 8; nt++)
            #pragma unroll
            for (int c = 0; c < 4; c++) sacc[nt][c] = 0.f;

        #pragma unroll
        for (int g4 = 0; g4 < 4; g4++) {
            const int kr = g4 * 16 + (lane & 15);
            const uint32_t swz = (uint32_t)(kr & 7) << 4;
            const uint32_t kb = sb + bufo + (uint32_t)kr * 256;
            #pragma unroll
            for (int ds = 0; ds < 8; ds++) {
                const uint32_t off = (((uint32_t)(ds * 32)) + cgo) ^ swz;
                uint32_t rh[4], rl[4];
                ldsm_x4(kb + off, rh);
                ldsm_x4(kb + 16384 + off, rl);
                uint32_t bh0[2] = {rh[0], rh[2]}, bh1[2] = {rh[1], rh[3]};
                uint32_t bl0[2] = {rl[0], rl[2]}, bl1[2] = {rl[1], rl[3]};
                mma_bf16(sacc[2 * g4 + 0], Aqh[ds], bh0);
                mma_bf16(sacc[2 * g4 + 0], Aqh[ds], bl0);
                mma_bf16(sacc[2 * g4 + 0], Aql[ds], bh0);
                mma_bf16(sacc[2 * g4 + 1], Aqh[ds], bh1);
                mma_bf16(sacc[2 * g4 + 1], Aqh[ds], bl1);
                mma_bf16(sacc[2 * g4 + 1], Aql[ds], bh1);
            }
        }

        // ---- scale + causal + key mask ----
        const int* mrow = reinterpret_cast<const int*>(smem + ATT_MASK + s * 256);
        #pragma unroll
        for (int nt = 0; nt < 8; nt++) {
            const int c0 = nt * 8 + (lane & 3) * 2;
            const int k0g = kv0 + c0, k1g = k0g + 1;
            const bool mv0 = mrow[c0] != 0, mv1 = mrow[c0 + 1] != 0;
            float v0 = sacc[nt][0] * scale, v1 = sacc[nt][1] * scale;
            float v2 = sacc[nt][2] * scale, v3 = sacc[nt][3] * scale;
            sacc[nt][0] = (k0g > r1g || !mv0) ? -1e9f : v0;
            sacc[nt][1] = (k1g > r1g || !mv1) ? -1e9f : v1;
            sacc[nt][2] = (k0g > r2g || !mv0) ? -1e9f : v2;
            sacc[nt][3] = (k1g > r2g || !mv1) ? -1e9f : v3;
        }

        // ---- online softmax ----
        float mx1 = -1e30f, mx2 = -1e30f;
        #pragma unroll
        for (int nt = 0; nt < 8; nt++) {
            mx1 = fmaxf(mx1, fmaxf(sacc[nt][0], sacc[nt][1]));
            mx2 = fmaxf(mx2, fmaxf(sacc[nt][2], sacc[nt][3]));
        }
        mx1 = fmaxf(mx1, __shfl_xor_sync(0xFFFFFFFFu, mx1, 1));
        mx1 = fmaxf(mx1, __shfl_xor_sync(0xFFFFFFFFu, mx1, 2));
        mx2 = fmaxf(mx2, __shfl_xor_sync(0xFFFFFFFFu, mx2, 1));
        mx2 = fmaxf(mx2, __shfl_xor_sync(0xFFFFFFFFu, mx2, 2));
        const float m1n = fmaxf(m1, mx1), m2n = fmaxf(m2, mx2);
        const float a1 = __expf(m1 - m1n), a2 = __expf(m2 - m2n);
        float s1 = 0.f, s2 = 0.f;
        #pragma unroll
        for (int nt = 0; nt < 8; nt++) {
            sacc[nt][0] = __expf(sacc[nt][0] - m1n);
            sacc[nt][1] = __expf(sacc[nt][1] - m1n);
            sacc[nt][2] = __expf(sacc[nt][2] - m2n);
            sacc[nt][3] = __expf(sacc[nt][3] - m2n);
            s1 += sacc[nt][0] + sacc[nt][1];
            s2 += sacc[nt][2] + sacc[nt][3];
        }
        s1 += __shfl_xor_sync(0xFFFFFFFFu, s1, 1);
        s1 += __shfl_xor_sync(0xFFFFFFFFu, s1, 2);
        s2 += __shfl_xor_sync(0xFFFFFFFFu, s2, 1);
        s2 += __shfl_xor_sync(0xFFFFFFFFu, s2, 2);
        l1 = l1 * a1 + s1; m1 = m1n;
        l2 = l2 * a2 + s2; m2 = m2n;
        #pragma unroll
        for (int nt = 0; nt < 16; nt++) {
            acc[nt][0] *= a1; acc[nt][1] *= a1;
            acc[nt][2] *= a2; acc[nt][3] *= a2;
        }

        // ---- O += P V (3-pass split) ----
        #pragma unroll
        for (int ks = 0; ks < 4; ks++) {
            const float* p0 = sacc[2 * ks];
            const float* p1 = sacc[2 * ks + 1];
            __nv_bfloat162 h0 = __floats2bfloat162_rn(p0[0], p0[1]);
            __nv_bfloat162 h1 = __floats2bfloat162_rn(p0[2], p0[3]);
            __nv_bfloat162 h2 = __floats2bfloat162_rn(p1[0], p1[1]);
            __nv_bfloat162 h3 = __floats2bfloat162_rn(p1[2], p1[3]);
            uint32_t pa_h[4] = {bf2_bits(h0), bf2_bits(h1), bf2_bits(h2), bf2_bits(h3)};
            __nv_bfloat162 e0 = __floats2bfloat162_rn(
                p0[0] - __bfloat162float(h0.x), p0[1] - __bfloat162float(h0.y));
            __nv_bfloat162 e1 = __floats2bfloat162_rn(
                p0[2] - __bfloat162float(h1.x), p0[3] - __bfloat162float(h1.y));
            __nv_bfloat162 e2 = __floats2bfloat162_rn(
                p1[0] - __bfloat162float(h2.x), p1[1] - __bfloat162float(h2.y));
            __nv_bfloat162 e3 = __floats2bfloat162_rn(
                p1[2] - __bfloat162float(h3.x), p1[3] - __bfloat162float(h3.y));
            uint32_t pa_l[4] = {bf2_bits(e0), bf2_bits(e1), bf2_bits(e2), bf2_bits(e3)};

            #pragma unroll
            for (int gd = 0; gd < 8; gd++) {
                const int dr = gd * 16 + (lane & 15);
                const uint32_t swz = (uint32_t)(dr & 7) << 4;
                const uint32_t off = (((uint32_t)(ks * 32)) + cgo) ^ swz;
                const uint32_t vb = sb + bufo + 32768 + (uint32_t)dr * 128;
                uint32_t rh[4], rl[4];
                ldsm_x4(vb + off, rh);
                ldsm_x4(vb + 16384 + off, rl);
                uint32_t bh0[2] = {rh[0], rh[2]}, bh1[2] = {rh[1], rh[3]};
                uint32_t bl0[2] = {rl[0], rl[2]}, bl1[2] = {rl[1], rl[3]};
                mma_bf16(acc[2 * gd + 0], pa_h, bh0);
                mma_bf16(acc[2 * gd + 0], pa_h, bl0);
                mma_bf16(acc[2 * gd + 0], pa_l, bh0);
                mma_bf16(acc[2 * gd + 1], pa_h, bh1);
                mma_bf16(acc[2 * gd + 1], pa_h, bl1);
                mma_bf16(acc[2 * gd + 1], pa_l, bh1);
            }
        }

        CPWAIT(0);
        __syncthreads();
    }

    // ---- epilogue: split-store O to bf16 hi/lo ----
    const float i1 = (l1 > 0.f) ? 1.f / l1 : 0.f;
    const float i2 = (l2 > 0.f) ? 1.f / l2 : 0.f;
    #pragma unroll
    for (int nt = 0; nt < 16; nt++) {
        const int col = nt * 8 + (lane & 3) * 2;
        {
            float o0 = acc[nt][0] * i1, o1 = acc[nt][1] * i1;
            __nv_bfloat162 hh = __floats2bfloat162_rn(o0, o1);
            __nv_bfloat162 ll = __floats2bfloat162_rn(
                o0 - __bfloat162float(hh.x), o1 - __bfloat162float(hh.y));
            size_t off = base + (size_t)r1g * D_MODEL + col;
            *reinterpret_cast<uint32_t*>(Oh + off) = bf2_bits(hh);
            *reinterpret_cast<uint32_t*>(Ol + off) = bf2_bits(ll);
        }
        {
            float o0 = acc[nt][2] * i2, o1 = acc[nt][3] * i2;
            __nv_bfloat162 hh = __floats2bfloat162_rn(o0, o1);
            __nv_bfloat162 ll = __floats2bfloat162_rn(
                o0 - __bfloat162float(hh.x), o1 - __bfloat162float(hh.y));
            size_t off = base + (size_t)r2g * D_MODEL + col;
            *reinterpret_cast<uint32_t*>(Oh + off) = bf2_bits(hh);
            *reinterpret_cast<uint32_t*>(Ol + off) = bf2_bits(ll);
        }
    }
}

// ---------------- launch -----------------------------------------------------
extern "C" void kernel_launch(void* const* d_in, const int* in_sizes, int n_in,
                              void* d_out, int out_size) {
    const float* x           = (const float*)d_in[0];
    const int*   attn_mask   = (const int*)  d_in[1];
    const float* w_norm_attn = (const float*)d_in[2];
    const float* wq          = (const float*)d_in[3];
    const float* wk          = (const float*)d_in[4];
    const float* wv          = (const float*)d_in[5];
    const float* wo          = (const float*)d_in[6];
    const float* w_norm_mlp  = (const float*)d_in[7];
    const float* w_up        = (const float*)d_in[8];
    const float* w_down      = (const float*)d_in[9];
    float* out = (float*)d_out;

    bf16 *h_hi, *h_lo, *q_hi, *q_lo, *k_hi, *k_lo, *v_hi, *v_lo;
    bf16 *att_hi, *att_lo, *up_hi, *up_lo;
    bf16 *wq_hi, *wq_lo, *wk_hi, *wk_lo, *wv_hi, *wv_lo, *wo_hi, *wo_lo;
    bf16 *wu_hi, *wu_lo, *wd_hi, *wd_lo;
    float* x1;
    cudaGetSymbolAddress((void**)&h_hi, g_h_hi);   cudaGetSymbolAddress((void**)&h_lo, g_h_lo);
    cudaGetSymbolAddress((void**)&q_hi, g_q_hi);   cudaGetSymbolAddress((void**)&q_lo, g_q_lo);
    cudaGetSymbolAddress((void**)&k_hi, g_k_hi);   cudaGetSymbolAddress((void**)&k_lo, g_k_lo);
    cudaGetSymbolAddress((void**)&v_hi, g_v_hi);   cudaGetSymbolAddress((void**)&v_lo, g_v_lo);
    cudaGetSymbolAddress((void**)&att_hi, g_att_hi); cudaGetSymbolAddress((void**)&att_lo, g_att_lo);
    cudaGetSymbolAddress((void**)&up_hi, g_up_hi); cudaGetSymbolAddress((void**)&up_lo, g_up_lo);
    cudaGetSymbolAddress((void**)&wq_hi, g_wq_hi); cudaGetSymbolAddress((void**)&wq_lo, g_wq_lo);
    cudaGetSymbolAddress((void**)&wk_hi, g_wk_hi); cudaGetSymbolAddress((void**)&wk_lo, g_wk_lo);
    cudaGetSymbolAddress((void**)&wv_hi, g_wv_hi); cudaGetSymbolAddress((void**)&wv_lo, g_wv_lo);
    cudaGetSymbolAddress((void**)&wo_hi, g_wo_hi); cudaGetSymbolAddress((void**)&wo_lo, g_wo_lo);
    cudaGetSymbolAddress((void**)&wu_hi, g_wu_hi); cudaGetSymbolAddress((void**)&wu_lo, g_wu_lo);
    cudaGetSymbolAddress((void**)&wd_hi, g_wd_hi); cudaGetSymbolAddress((void**)&wd_lo, g_wd_lo);
    cudaGetSymbolAddress((void**)&x1, g_x1);

    cudaFuncSetAttribute(flash_attn_tc,
                         cudaFuncAttributeMaxDynamicSharedMemorySize, ATT_SMEM_BYTES);
    cudaFuncSetAttribute(mma_gemm<0>,
                         cudaFuncAttributeMaxDynamicSharedMemorySize, GEMM_SMEM);
    cudaFuncSetAttribute(mma_gemm<1>,
                         cudaFuncAttributeMaxDynamicSharedMemorySize, GEMM_SMEM);
    cudaFuncSetAttribute(mma_gemm<2>,
                         cudaFuncAttributeMaxDynamicSharedMemorySize, GEMM_SMEM);

    // 0) split weights to bf16 hi/lo
    const int DD4 = D_MODEL * D_MODEL / 4;
    const int UD4 = MLP_DIM * D_MODEL / 4;
    split_fp32<<<(DD4 + 255) / 256, 256>>>(wq, wq_hi, wq_lo, DD4);
    split_fp32<<<(DD4 + 255) / 256, 256>>>(wk, wk_hi, wk_lo, DD4);
    split_fp32<<<(DD4 + 255) / 256, 256>>>(wv, wv_hi, wv_lo, DD4);
    split_fp32<<<(DD4 + 255) / 256, 256>>>(wo, wo_hi, wo_lo, DD4);
    split_fp32<<<(UD4 + 255) / 256, 256>>>(w_up, wu_hi, wu_lo, UD4);
    split_fp32<<<(UD4 + 255) / 256, 256>>>(w_down, wd_hi, wd_lo, UD4);

    // 1) rmsnorm(x) -> h (bf16 hi/lo)
    rmsnorm_split<<<TOK, 256>>>(x, w_norm_attn, h_hi, h_lo);

    // 2) q, k, v projections (split-store epilogue)
    dim3 gD(D_MODEL / 128, TOK / 128);
    mma_gemm<0><<<gD, 256, GEMM_SMEM>>>(TOK, D_MODEL, D_MODEL,
        h_hi, h_lo, wq_hi, wq_lo, nullptr, nullptr, q_hi, q_lo);
    mma_gemm<0><<<gD, 256, GEMM_SMEM>>>(TOK, D_MODEL, D_MODEL,
        h_hi, h_lo, wk_hi, wk_lo, nullptr, nullptr, k_hi, k_lo);
    mma_gemm<0><<<gD, 256, GEMM_SMEM>>>(TOK, D_MODEL, D_MODEL,
        h_hi, h_lo, wv_hi, wv_lo, nullptr, nullptr, v_hi, v_lo);

    // 3) attention (bf16 split in/out)
    dim3 gA(SEQ / 128, N_HEADS, BATCH);
    flash_attn_tc<<<gA, 256, ATT_SMEM_BYTES>>>(q_hi, q_lo, k_hi, k_lo,
                                               v_hi, v_lo, attn_mask,
                                               att_hi, att_lo);

    // 4) output projection + residual -> x1 (fp32)
    mma_gemm<2><<<gD, 256, GEMM_SMEM>>>(TOK, D_MODEL, D_MODEL,
        att_hi, att_lo, wo_hi, wo_lo, x, x1, nullptr, nullptr);

    // 5) rmsnorm(x1) -> h (bf16 hi/lo)
    rmsnorm_split<<<TOK, 256>>>(x1, w_norm_mlp, h_hi, h_lo);

    // 6) up projection + gelu (split-store)
    dim3 gU(MLP_DIM / 128, TOK / 128);
    mma_gemm<1><<<gU, 256, GEMM_SMEM>>>(TOK, MLP_DIM, D_MODEL,
        h_hi, h_lo, wu_hi, wu_lo, nullptr, nullptr, up_hi, up_lo);

    // 7) down projection + residual -> out (fp32)
    mma_gemm<2><<<gD, 256, GEMM_SMEM>>>(TOK, D_MODEL, MLP_DIM,
        up_hi, up_lo, wd_hi, wd_lo, x1, out, nullptr, nullptr);
}

// round 6
// speedup vs baseline: 1.1549x; 1.1549x over previous
#include <cuda_runtime.h>
#include <cuda_bf16.h>
#include <math.h>
#include <stdint.h>

#define D_MODEL 2048
#define N_HEADS 16
#define HEAD_DIM 128
#define MLP_DIM 8192
#define BATCH 2
#define SEQ 2048
#define TOK (BATCH * SEQ)

typedef __nv_bfloat16 bf16;

// ---------------- scratch (static device globals) ---------------------------
__device__ bf16 g_h_hi[(size_t)TOK * D_MODEL],  g_h_lo[(size_t)TOK * D_MODEL];
__device__ bf16 g_q_hi[(size_t)TOK * D_MODEL],  g_q_lo[(size_t)TOK * D_MODEL];
__device__ bf16 g_k_hi[(size_t)TOK * D_MODEL],  g_k_lo[(size_t)TOK * D_MODEL];
__device__ bf16 g_v_hi[(size_t)TOK * D_MODEL],  g_v_lo[(size_t)TOK * D_MODEL];
__device__ bf16 g_att_hi[(size_t)TOK * D_MODEL], g_att_lo[(size_t)TOK * D_MODEL];
__device__ bf16 g_up_hi[(size_t)TOK * MLP_DIM], g_up_lo[(size_t)TOK * MLP_DIM];
__device__ bf16 g_wq_hi[(size_t)D_MODEL * D_MODEL], g_wq_lo[(size_t)D_MODEL * D_MODEL];
__device__ bf16 g_wk_hi[(size_t)D_MODEL * D_MODEL], g_wk_lo[(size_t)D_MODEL * D_MODEL];
__device__ bf16 g_wv_hi[(size_t)D_MODEL * D_MODEL], g_wv_lo[(size_t)D_MODEL * D_MODEL];
__device__ bf16 g_wo_hi[(size_t)D_MODEL * D_MODEL], g_wo_lo[(size_t)D_MODEL * D_MODEL];
__device__ bf16 g_wu_hi[(size_t)MLP_DIM * D_MODEL], g_wu_lo[(size_t)MLP_DIM * D_MODEL];
__device__ bf16 g_wd_hi[(size_t)D_MODEL * MLP_DIM], g_wd_lo[(size_t)D_MODEL * MLP_DIM];
__device__ float g_x1[(size_t)TOK * D_MODEL];

// ================= PTX helpers (baseline PTX, sm_80+) =======================
__device__ __forceinline__ uint32_t smem_to_u32(const void* p) {
    uint32_t a;
    asm("{ .reg .u64 t; cvta.to.shared.u64 t, %1; cvt.u32.u64 %0, t; }"
        : "=r"(a) : "l"(p));
    return a;
}
__device__ __forceinline__ void ldsm_x4(uint32_t addr, uint32_t* r) {
    asm volatile("ldmatrix.sync.aligned.m8n8.x4.shared.b16 {%0,%1,%2,%3}, [%4];"
                 : "=r"(r[0]), "=r"(r[1]), "=r"(r[2]), "=r"(r[3]) : "r"(addr));
}
__device__ __forceinline__ void mma_bf16(float* d, const uint32_t* a,
                                         const uint32_t* b) {
    asm volatile(
        "mma.sync.aligned.m16n8k16.row.col.f32.bf16.bf16.f32 "
        "{%0,%1,%2,%3}, {%4,%5,%6,%7}, {%8,%9}, {%0,%1,%2,%3};"
        : "+f"(d[0]), "+f"(d[1]), "+f"(d[2]), "+f"(d[3])
        : "r"(a[0]), "r"(a[1]), "r"(a[2]), "r"(a[3]), "r"(b[0]), "r"(b[1]));
}
__device__ __forceinline__ uint32_t bf2_bits(__nv_bfloat162 v) {
    return *reinterpret_cast<uint32_t*>(&v);
}
#define CP16(dst, src) \
    asm volatile("cp.async.cg.shared.global [%0], [%1], 16;" \
                 :: "r"(dst), "l"(src) : "memory")
#define CPCOMMIT() asm volatile("cp.async.commit_group;" ::: "memory")
#define CPWAIT(n)  asm volatile("cp.async.wait_group %0;" :: "n"(n) : "memory")

// ================= fp32 -> bf16 hi/lo split (weights; 2 launches) ===========
__device__ __forceinline__ void split_store(const float* src, bf16* hi, bf16* lo,
                                            int i) {
    float4 v = reinterpret_cast<const float4*>(src)[i];
    __nv_bfloat162 h01 = __floats2bfloat162_rn(v.x, v.y);
    __nv_bfloat162 h23 = __floats2bfloat162_rn(v.z, v.w);
    __nv_bfloat162 l01 = __floats2bfloat162_rn(v.x - __bfloat162float(h01.x),
                                               v.y - __bfloat162float(h01.y));
    __nv_bfloat162 l23 = __floats2bfloat162_rn(v.z - __bfloat162float(h23.x),
                                               v.w - __bfloat162float(h23.y));
    reinterpret_cast<uint2*>(hi)[i] = make_uint2(bf2_bits(h01), bf2_bits(h23));
    reinterpret_cast<uint2*>(lo)[i] = make_uint2(bf2_bits(l01), bf2_bits(l23));
}

__global__ void split_dd(const float* __restrict__ wq, const float* __restrict__ wk,
                         const float* __restrict__ wv, const float* __restrict__ wo,
                         bf16* qh, bf16* ql, bf16* kh, bf16* kl,
                         bf16* vh, bf16* vl, bf16* oh, bf16* ol) {
    int i = blockIdx.x * blockDim.x + threadIdx.x;
    if (i >= D_MODEL * D_MODEL / 4) return;
    switch (blockIdx.y) {
        case 0: split_store(wq, qh, ql, i); break;
        case 1: split_store(wk, kh, kl, i); break;
        case 2: split_store(wv, vh, vl, i); break;
        default: split_store(wo, oh, ol, i); break;
    }
}
__global__ void split_ud(const float* __restrict__ wu, const float* __restrict__ wd,
                         bf16* uh, bf16* ul, bf16* dh, bf16* dl) {
    int i = blockIdx.x * blockDim.x + threadIdx.x;
    if (i >= MLP_DIM * D_MODEL / 4) return;
    if (blockIdx.y == 0) split_store(wu, uh, ul, i);
    else                 split_store(wd, dh, dl, i);
}

// ================= RMSNorm -> bf16 hi/lo =====================================
__global__ void rmsnorm_split(const float* __restrict__ x,
                              const float* __restrict__ w,
                              bf16* __restrict__ hi, bf16* __restrict__ lo) {
    int row = blockIdx.x;
    const float4* xr = reinterpret_cast<const float4*>(x + (size_t)row * D_MODEL);
    const float4* w4 = reinterpret_cast<const float4*>(w);

    float ss = 0.f;
    for (int i = threadIdx.x; i < D_MODEL / 4; i += blockDim.x) {
        float4 v = xr[i];
        ss += v.x * v.x + v.y * v.y + v.z * v.z + v.w * v.w;
    }
    for (int off = 16; off > 0; off >>= 1)
        ss += __shfl_xor_sync(0xFFFFFFFFu, ss, off);
    __shared__ float red[8];
    __shared__ float s_rms;
    int lane = threadIdx.x & 31, wid = threadIdx.x >> 5;
    if (lane == 0) red[wid] = ss;
    __syncthreads();
    if (threadIdx.x == 0) {
        float tt = 0.f;
        #pragma unroll
        for (int i = 0; i < 8; i++) tt += red[i];
        s_rms = rsqrtf(tt / (float)D_MODEL + 1e-6f);
    }
    __syncthreads();
    float r = s_rms;
    uint2* h2 = reinterpret_cast<uint2*>(hi + (size_t)row * D_MODEL);
    uint2* l2 = reinterpret_cast<uint2*>(lo + (size_t)row * D_MODEL);
    for (int i = threadIdx.x; i < D_MODEL / 4; i += blockDim.x) {
        float4 v = xr[i];
        float4 ww = w4[i];
        float y0 = v.x * r * ww.x, y1 = v.y * r * ww.y;
        float y2 = v.z * r * ww.z, y3 = v.w * r * ww.w;
        __nv_bfloat162 h01 = __floats2bfloat162_rn(y0, y1);
        __nv_bfloat162 h23 = __floats2bfloat162_rn(y2, y3);
        __nv_bfloat162 l01 = __floats2bfloat162_rn(y0 - __bfloat162float(h01.x),
                                                   y1 - __bfloat162float(h01.y));
        __nv_bfloat162 l23 = __floats2bfloat162_rn(y2 - __bfloat162float(h23.x),
                                                   y3 - __bfloat162float(h23.y));
        h2[i] = make_uint2(bf2_bits(h01), bf2_bits(h23));
        l2[i] = make_uint2(bf2_bits(l01), bf2_bits(l23));
    }
}

// ================= bf16-split GEMM via mma.sync + cp.async ===================
// C = A @ B^T with A = Ah+Al, B = Bh+Bl; acc += Ah*Bh + Ah*Bl + Al*Bh.
// EPI: 0 = split-store bf16 hi/lo, 1 = gelu + split-store, 2 = residual fp32
#define KC 32
#define ROWB 128
#define TILE_B (128 * ROWB)       // 16 KB
#define STAGE_B (2 * TILE_B)      // 32 KB (A+B)
#define NSTAGE 3
#define GEMM_SMEM (NSTAGE * STAGE_B)  // 96 KB -> 2 CTAs/SM

template <int EPI>
__global__ void __launch_bounds__(256, 2)
mma_gemm(int M, int N, int K,
         const bf16* __restrict__ Ah_, const bf16* __restrict__ Al_,
         const bf16* __restrict__ Bh_, const bf16* __restrict__ Bl_,
         const float* __restrict__ RES, float* __restrict__ Cf,
         bf16* __restrict__ Ch, bf16* __restrict__ Cl) {
    extern __shared__ char smem[];
    const uint32_t su = smem_to_u32(smem);

    const int t = threadIdx.x;
    const int lane = t & 31;
    const int wid = t >> 5;
    const int wm = wid & 3;
    const int wn = wid >> 2;
    const int m0 = blockIdx.y * 128;
    const int n0 = blockIdx.x * 128;

    const int lrow = t >> 1;
    const int half = t & 1;
    const bf16* Asrc = (half ? Al_ : Ah_) + (size_t)(m0 + lrow) * K;
    const bf16* Bsrc = (half ? Bl_ : Bh_) + (size_t)(n0 + lrow) * K;
    const uint32_t sw = (uint32_t)(lrow & 7) << 4;
    const uint32_t drow = (uint32_t)lrow * ROWB;

    auto CP_chunk = [&](int s, int k0) {
        const uint32_t stA = su + (uint32_t)s * STAGE_B;
        const uint32_t stB = stA + TILE_B;
        #pragma unroll
        for (int c = 0; c < 4; c++) {
            const uint32_t d = drow + (((uint32_t)(half * 64 + c * 16)) ^ sw);
            CP16(stA + d, Asrc + k0 + c * 8);
            CP16(stB + d, Bsrc + k0 + c * 8);
        }
    };

    float acc[2][8][4];
    #pragma unroll
    for (int mt = 0; mt < 2; mt++)
        #pragma unroll
        for (int nt = 0; nt < 8; nt++)
            #pragma unroll
            for (int j = 0; j < 4; j++) acc[mt][nt][j] = 0.f;

    const int nch = K / KC;
    #pragma unroll
    for (int s = 0; s < NSTAGE - 1; s++) {
        CP_chunk(s, s * KC);
        CPCOMMIT();
    }

    const int lrow16 = lane & 15;
    const int cg = (lane >> 4) & 1;

    for (int i = 0; i < nch; i++) {
        CPWAIT(NSTAGE - 2);
        __syncthreads();

        const uint32_t sA = su + (uint32_t)(i % NSTAGE) * STAGE_B;
        const uint32_t sB = sA + TILE_B;

        #pragma unroll
        for (int ks = 0; ks < 2; ks++) {
            const uint32_t cbh = (uint32_t)(ks * 32 + cg * 16);
            uint32_t Ahf[2][4], Alf[2][4];
            #pragma unroll
            for (int mt = 0; mt < 2; mt++) {
                const int row = wm * 32 + mt * 16 + lrow16;
                const uint32_t swz = (uint32_t)(row & 7) << 4;
                const uint32_t base = sA + (uint32_t)row * ROWB;
                ldsm_x4(base + (cbh ^ swz), Ahf[mt]);
                ldsm_x4(base + ((cbh + 64) ^ swz), Alf[mt]);
            }
            #pragma unroll
            for (int q = 0; q < 4; q++) {
                const int row = wn * 64 + q * 16 + lrow16;
                const uint32_t swz = (uint32_t)(row & 7) << 4;
                const uint32_t base = sB + (uint32_t)row * ROWB;
                uint32_t rh[4], rl[4];
                ldsm_x4(base + (cbh ^ swz), rh);
                ldsm_x4(base + ((cbh + 64) ^ swz), rl);
                uint32_t bh0[2] = {rh[0], rh[2]};
                uint32_t bh1[2] = {rh[1], rh[3]};
                uint32_t bl0[2] = {rl[0], rl[2]};
                uint32_t bl1[2] = {rl[1], rl[3]};
                #pragma unroll
                for (int mt = 0; mt < 2; mt++) {
                    mma_bf16(acc[mt][2 * q + 0], Ahf[mt], bh0);
                    mma_bf16(acc[mt][2 * q + 0], Ahf[mt], bl0);
                    mma_bf16(acc[mt][2 * q + 0], Alf[mt], bh0);
                    mma_bf16(acc[mt][2 * q + 1], Ahf[mt], bh1);
                    mma_bf16(acc[mt][2 * q + 1], Ahf[mt], bl1);
                    mma_bf16(acc[mt][2 * q + 1], Alf[mt], bh1);
                }
            }
        }

        if (i + NSTAGE - 1 < nch) {
            CP_chunk((i + NSTAGE - 1) % NSTAGE, (i + NSTAGE - 1) * KC);
        }
        CPCOMMIT();
    }

    // ---- epilogue ----
    const int er0 = m0 + wm * 32 + (lane >> 2);
    const int ec0 = n0 + wn * 64 + (lane & 3) * 2;
    #pragma unroll
    for (int mt = 0; mt < 2; mt++) {
        #pragma unroll
        for (int g = 0; g < 2; g++) {
            const int row = er0 + mt * 16 + g * 8;
            #pragma unroll
            for (int nt = 0; nt < 8; nt++) {
                const int col = ec0 + nt * 8;
                float v0 = acc[mt][nt][g * 2 + 0];
                float v1 = acc[mt][nt][g * 2 + 1];
                size_t roff = (size_t)row * N + col;
                if (EPI == 2) {
                    float2 r = *reinterpret_cast<const float2*>(RES + roff);
                    *reinterpret_cast<float2*>(Cf + roff) =
                        make_float2(v0 + r.x, v1 + r.y);
                } else {
                    if (EPI == 1) {
                        v0 = 0.5f * v0 * (1.0f + erff(v0 * 0.70710678118654752f));
                        v1 = 0.5f * v1 * (1.0f + erff(v1 * 0.70710678118654752f));
                    }
                    __nv_bfloat162 hh = __floats2bfloat162_rn(v0, v1);
                    __nv_bfloat162 ll = __floats2bfloat162_rn(
                        v0 - __bfloat162float(hh.x), v1 - __bfloat162float(hh.y));
                    *reinterpret_cast<uint32_t*>(Ch + roff) = bf2_bits(hh);
                    *reinterpret_cast<uint32_t*>(Cl + roff) = bf2_bits(ll);
                }
            }
        }
    }
}

// ================= tensor-core flash attention (bf16 split inputs) ===========
#define ATT_BUF0 65536
#define ATT_MASK 131072
#define ATT_SMEM_BYTES (131072 + 512)

__device__ __forceinline__ void att_stage_chunk(
    char* smem, uint32_t sb, uint32_t bufoff,
    const bf16* __restrict__ Kh, const bf16* __restrict__ Kl,
    const bf16* __restrict__ Vh, const bf16* __restrict__ Vl,
    const int* __restrict__ bm, int kv0, int slot, int t) {
    // K tile via cp.async: row = t>>2 (0..63), dq = (t&3)*32 d-values
    {
        const int row = t >> 2;
        const int dq = (t & 3) * 32;
        const size_t goff = (size_t)(kv0 + row) * D_MODEL + dq;
        const uint32_t rbase = sb + bufoff + (uint32_t)row * 256;
        const uint32_t swr = (uint32_t)(row & 7) << 4;
        #pragma unroll
        for (int i = 0; i < 4; i++) {
            const uint32_t off = ((uint32_t)(dq * 2 + i * 16)) ^ swr;
            CP16(rbase + off, Kh + goff + i * 8);
            CP16(rbase + 16384 + off, Kl + goff + i * 8);
        }
    }
    // Vt tile: transpose V[kv][d] -> Vt[d][kv]; uint4 loads, byte_perm repack
    {
        const int kvp = t & 31;     // kv pair index
        const int dblk = t >> 5;    // 16 d-values per thread
        const size_t r0 = (size_t)(kv0 + 2 * kvp) * D_MODEL + dblk * 16;
        const size_t r1 = r0 + D_MODEL;
        uint4 h0a = *reinterpret_cast<const uint4*>(Vh + r0);
        uint4 h0b = *reinterpret_cast<const uint4*>(Vh + r0 + 8);
        uint4 h1a = *reinterpret_cast<const uint4*>(Vh + r1);
        uint4 h1b = *reinterpret_cast<const uint4*>(Vh + r1 + 8);
        uint4 l0a = *reinterpret_cast<const uint4*>(Vl + r0);
        uint4 l0b = *reinterpret_cast<const uint4*>(Vl + r0 + 8);
        uint4 l1a = *reinterpret_cast<const uint4*>(Vl + r1);
        uint4 l1b = *reinterpret_cast<const uint4*>(Vl + r1 + 8);
        uint32_t h0[8] = {h0a.x, h0a.y, h0a.z, h0a.w, h0b.x, h0b.y, h0b.z, h0b.w};
        uint32_t h1[8] = {h1a.x, h1a.y, h1a.z, h1a.w, h1b.x, h1b.y, h1b.z, h1b.w};
        uint32_t l0[8] = {l0a.x, l0a.y, l0a.z, l0a.w, l0b.x, l0b.y, l0b.z, l0b.w};
        uint32_t l1[8] = {l1a.x, l1a.y, l1a.z, l1a.w, l1b.x, l1b.y, l1b.z, l1b.w};
        const uint32_t koff = (uint32_t)(kvp * 4);
        #pragma unroll
        for (int dd = 0; dd < 8; dd++) {
            const int d0 = dblk * 16 + dd * 2;
            const uint32_t vb0 = sb + bufoff + 32768 + (uint32_t)d0 * 128 +
                                 (koff ^ ((uint32_t)(d0 & 7) << 4));
            const uint32_t vb1 = sb + bufoff + 32768 + (uint32_t)(d0 + 1) * 128 +
                                 (koff ^ ((uint32_t)((d0 + 1) & 7) << 4));
            asm volatile("st.shared.b32 [%0], %1;" :: "r"(vb0),
                         "r"(__byte_perm(h0[dd], h1[dd], 0x5410)) : "memory");
            asm volatile("st.shared.b32 [%0], %1;" :: "r"(vb1),
                         "r"(__byte_perm(h0[dd], h1[dd], 0x7632)) : "memory");
            asm volatile("st.shared.b32 [%0], %1;" :: "r"(vb0 + 16384),
                         "r"(__byte_perm(l0[dd], l1[dd], 0x5410)) : "memory");
            asm volatile("st.shared.b32 [%0], %1;" :: "r"(vb1 + 16384),
                         "r"(__byte_perm(l0[dd], l1[dd], 0x7632)) : "memory");
        }
    }
    if (t < 64)
        reinterpret_cast<int*>(smem + ATT_MASK + slot * 256)[t] = bm[kv0 + t];
}

__global__ void __launch_bounds__(256, 1)
flash_attn_tc(const bf16* __restrict__ Qh, const bf16* __restrict__ Ql,
              const bf16* __restrict__ Kh, const bf16* __restrict__ Kl,
              const bf16* __restrict__ Vh, const bf16* __restrict__ Vl,
              const int* __restrict__ mask,
              bf16* __restrict__ Oh, bf16* __restrict__ Ol) {
    extern __shared__ char smem[];
    const uint32_t sb = smem_to_u32(smem);
    const int t = threadIdx.x, lane = t & 31, w = t >> 5;
    const int qi = gridDim.x - 1 - blockIdx.x;  // longest-work CTAs first
    const int h = blockIdx.y, b = blockIdx.z;
    const int q0 = qi * 128;
    const size_t base = (size_t)b * SEQ * D_MODEL + (size_t)h * HEAD_DIM;
    const int* bm = mask + b * SEQ;
    const float scale = 0.08838834764831845f;  // 1/sqrt(128)

    // ---- stage Q (plain copies from bf16 hi/lo) ----
    {
        const int row = t >> 1, half = t & 1;
        const size_t goff = base + (size_t)(q0 + row) * D_MODEL + half * 64;
        const uint4* ghv = reinterpret_cast<const uint4*>(Qh + goff);
        const uint4* glv = reinterpret_cast<const uint4*>(Ql + goff);
        char* qr = smem + (uint32_t)row * 256;
        const uint32_t swr = (uint32_t)(row & 7) << 4;
        #pragma unroll
        for (int i = 0; i < 8; i++) {
            const uint32_t off = ((uint32_t)(half * 128 + i * 16)) ^ swr;
            *reinterpret_cast<uint4*>(qr + off) = ghv[i];
            *reinterpret_cast<uint4*>(qr + 32768 + off) = glv[i];
        }
    }
    att_stage_chunk(smem, sb, ATT_BUF0, Kh + base, Kl + base,
                    Vh + base, Vl + base, bm, 0, 0, t);
    CPCOMMIT();
    CPWAIT(0);
    __syncthreads();

    // ---- preload Q fragments (constant across KV chunks) ----
    uint32_t Aqh[8][4], Aql[8][4];
    {
        const int r = w * 16 + (lane & 15);
        const uint32_t swz = (uint32_t)(r & 7) << 4;
        const uint32_t cgo = ((uint32_t)(lane >> 4)) << 4;
        const uint32_t qb = sb + (uint32_t)r * 256;
        #pragma unroll
        for (int ds = 0; ds < 8; ds++) {
            const uint32_t off = (((uint32_t)(ds * 32)) + cgo) ^ swz;
            ldsm_x4(qb + off, Aqh[ds]);
            ldsm_x4(qb + 32768 + off, Aql[ds]);
        }
    }
    __syncthreads();  // Q frags read before chunk-1 staging may overwrite

    float m1 = -1e30f, l1 = 0.f, m2 = -1e30f, l2 = 0.f;
    float acc[16][4];
    #pragma unroll
    for (int nt = 0; nt < 16; nt++)
        #pragma unroll
        for (int c = 0; c < 4; c++) acc[nt][c] = 0.f;

    const int r1g = q0 + w * 16 + (lane >> 2);
    const int r2g = r1g + 8;
    const int nch = 2 * qi + 2;
    const uint32_t cgo = ((uint32_t)(lane >> 4)) << 4;

    for (int j = 0; j < nch; j++) {
        const int s = j & 1;
        const uint32_t bufo = s ? 0u : (uint32_t)ATT_BUF0;
        const int kv0 = j * 64;

        // stage chunk j+1 into the other buffer (overlaps with compute below)
        if (j + 1 < nch) {
            att_stage_chunk(smem, sb, s ? (uint32_t)ATT_BUF0 : 0u,
                            Kh + base, Kl + base, Vh + base, Vl + base,
                            bm, kv0 + 64, (j + 1) & 1, t);
            CPCOMMIT();
        }

        // ---- scores S = Q K^T (3-pass split) ----
        float sacc[8][4];
        #pragma unroll
        for (int nt = 0; nt < 8; nt++)
            #pragma unroll
            for (int c = 0; c < 4; c++) sacc[nt][c] = 0.f;

        #pragma unroll
        for (int g4 = 0; g4 < 4; g4++) {
            const int kr = g4 * 16 + (lane & 15);
            const uint32_t swz = (uint32_t)(kr & 7) << 4;
            const uint32_t kb = sb + bufo + (uint32_t)kr * 256;
            #pragma unroll
            for (int ds = 0; ds < 8; ds++) {
                const uint32_t off = (((uint32_t)(ds * 32)) + cgo) ^ swz;
                uint32_t rh[4], rl[4];
                ldsm_x4(kb + off, rh);
                ldsm_x4(kb + 16384 + off, rl);
                uint32_t bh0[2] = {rh[0], rh[2]}, bh1[2] = {rh[1], rh[3]};
                uint32_t bl0[2] = {rl[0], rl[2]}, bl1[2] = {rl[1], rl[3]};
                mma_bf16(sacc[2 * g4 + 0], Aqh[ds], bh0);
                mma_bf16(sacc[2 * g4 + 0], Aqh[ds], bl0);
                mma_bf16(sacc[2 * g4 + 0], Aql[ds], bh0);
                mma_bf16(sacc[2 * g4 + 1], Aqh[ds], bh1);
                mma_bf16(sacc[2 * g4 + 1], Aqh[ds], bl1);
                mma_bf16(sacc[2 * g4 + 1], Aql[ds], bh1);
            }
        }

        // ---- scale + causal + key mask ----
        const int* mrow = reinterpret_cast<const int*>(smem + ATT_MASK + s * 256);
        #pragma unroll
        for (int nt = 0; nt < 8; nt++) {
            const int c0 = nt * 8 + (lane & 3) * 2;
            const int k0g = kv0 + c0, k1g = k0g + 1;
            const bool mv0 = mrow[c0] != 0, mv1 = mrow[c0 + 1] != 0;
            float v0 = sacc[nt][0] * scale, v1 = sacc[nt][1] * scale;
            float v2 = sacc[nt][2] * scale, v3 = sacc[nt][3] * scale;
            sacc[nt][0] = (k0g > r1g || !mv0) ? -1e9f : v0;
            sacc[nt][1] = (k1g > r1g || !mv1) ? -1e9f : v1;
            sacc[nt][2] = (k0g > r2g || !mv0) ? -1e9f : v2;
            sacc[nt][3] = (k1g > r2g || !mv1) ? -1e9f : v3;
        }

        // ---- online softmax ----
        float mx1 = -1e30f, mx2 = -1e30f;
        #pragma unroll
        for (int nt = 0; nt < 8; nt++) {
            mx1 = fmaxf(mx1, fmaxf(sacc[nt][0], sacc[nt][1]));
            mx2 = fmaxf(mx2, fmaxf(sacc[nt][2], sacc[nt][3]));
        }
        mx1 = fmaxf(mx1, __shfl_xor_sync(0xFFFFFFFFu, mx1, 1));
        mx1 = fmaxf(mx1, __shfl_xor_sync(0xFFFFFFFFu, mx1, 2));
        mx2 = fmaxf(mx2, __shfl_xor_sync(0xFFFFFFFFu, mx2, 1));
        mx2 = fmaxf(mx2, __shfl_xor_sync(0xFFFFFFFFu, mx2, 2));
        const float m1n = fmaxf(m1, mx1), m2n = fmaxf(m2, mx2);
        const float a1 = __expf(m1 - m1n), a2 = __expf(m2 - m2n);
        float s1 = 0.f, s2 = 0.f;
        #pragma unroll
        for (int nt = 0; nt < 8; nt++) {
            sacc[nt][0] = __expf(sacc[nt][0] - m1n);
            sacc[nt][1] = __expf(sacc[nt][1] - m1n);
            sacc[nt][2] = __expf(sacc[nt][2] - m2n);
            sacc[nt][3] = __expf(sacc[nt][3] - m2n);
            s1 += sacc[nt][0] + sacc[nt][1];
            s2 += sacc[nt][2] + sacc[nt][3];
        }
        s1 += __shfl_xor_sync(0xFFFFFFFFu, s1, 1);
        s1 += __shfl_xor_sync(0xFFFFFFFFu, s1, 2);
        s2 += __shfl_xor_sync(0xFFFFFFFFu, s2, 1);
        s2 += __shfl_xor_sync(0xFFFFFFFFu, s2, 2);
        l1 = l1 * a1 + s1; m1 = m1n;
        l2 = l2 * a2 + s2; m2 = m2n;
        #pragma unroll
        for (int nt = 0; nt < 16; nt++) {
            acc[nt][0] *= a1; acc[nt][1] *= a1;
            acc[nt][2] *= a2; acc[nt][3] *= a2;
        }

        // ---- O += P V (3-pass split) ----
        #pragma unroll
        for (int ks = 0; ks < 4; ks++) {
            const float* p0 = sacc[2 * ks];
            const float* p1 = sacc[2 * ks + 1];
            __nv_bfloat162 h0 = __floats2bfloat162_rn(p0[0], p0[1]);
            __nv_bfloat162 h1 = __floats2bfloat162_rn(p0[2], p0[3]);
            __nv_bfloat162 h2 = __floats2bfloat162_rn(p1[0], p1[1]);
            __nv_bfloat162 h3 = __floats2bfloat162_rn(p1[2], p1[3]);
            uint32_t pa_h[4] = {bf2_bits(h0), bf2_bits(h1), bf2_bits(h2), bf2_bits(h3)};
            __nv_bfloat162 e0 = __floats2bfloat162_rn(
                p0[0] - __bfloat162float(h0.x), p0[1] - __bfloat162float(h0.y));
            __nv_bfloat162 e1 = __floats2bfloat162_rn(
                p0[2] - __bfloat162float(h1.x), p0[3] - __bfloat162float(h1.y));
            __nv_bfloat162 e2 = __floats2bfloat162_rn(
                p1[0] - __bfloat162float(h2.x), p1[1] - __bfloat162float(h2.y));
            __nv_bfloat162 e3 = __floats2bfloat162_rn(
                p1[2] - __bfloat162float(h3.x), p1[3] - __bfloat162float(h3.y));
            uint32_t pa_l[4] = {bf2_bits(e0), bf2_bits(e1), bf2_bits(e2), bf2_bits(e3)};

            #pragma unroll
            for (int gd = 0; gd < 8; gd++) {
                const int dr = gd * 16 + (lane & 15);
                const uint32_t swz = (uint32_t)(dr & 7) << 4;
                const uint32_t off = (((uint32_t)(ks * 32)) + cgo) ^ swz;
                const uint32_t vb = sb + bufo + 32768 + (uint32_t)dr * 128;
                uint32_t rh[4], rl[4];
                ldsm_x4(vb + off, rh);
                ldsm_x4(vb + 16384 + off, rl);
                uint32_t bh0[2] = {rh[0], rh[2]}, bh1[2] = {rh[1], rh[3]};
                uint32_t bl0[2] = {rl[0], rl[2]}, bl1[2] = {rl[1], rl[3]};
                mma_bf16(acc[2 * gd + 0], pa_h, bh0);
                mma_bf16(acc[2 * gd + 0], pa_h, bl0);
                mma_bf16(acc[2 * gd + 0], pa_l, bh0);
                mma_bf16(acc[2 * gd + 1], pa_h, bh1);
                mma_bf16(acc[2 * gd + 1], pa_h, bl1);
                mma_bf16(acc[2 * gd + 1], pa_l, bh1);
            }
        }

        CPWAIT(0);
        __syncthreads();
    }

    // ---- epilogue: split-store O to bf16 hi/lo ----
    const float i1 = (l1 > 0.f) ? 1.f / l1 : 0.f;
    const float i2 = (l2 > 0.f) ? 1.f / l2 : 0.f;
    #pragma unroll
    for (int nt = 0; nt < 16; nt++) {
        const int col = nt * 8 + (lane & 3) * 2;
        {
            float o0 = acc[nt][0] * i1, o1 = acc[nt][1] * i1;
            __nv_bfloat162 hh = __floats2bfloat162_rn(o0, o1);
            __nv_bfloat162 ll = __floats2bfloat162_rn(
                o0 - __bfloat162float(hh.x), o1 - __bfloat162float(hh.y));
            size_t off = base + (size_t)r1g * D_MODEL + col;
            *reinterpret_cast<uint32_t*>(Oh + off) = bf2_bits(hh);
            *reinterpret_cast<uint32_t*>(Ol + off) = bf2_bits(ll);
        }
        {
            float o0 = acc[nt][2] * i2, o1 = acc[nt][3] * i2;
            __nv_bfloat162 hh = __floats2bfloat162_rn(o0, o1);
            __nv_bfloat162 ll = __floats2bfloat162_rn(
                o0 - __bfloat162float(hh.x), o1 - __bfloat162float(hh.y));
            size_t off = base + (size_t)r2g * D_MODEL + col;
            *reinterpret_cast<uint32_t*>(Oh + off) = bf2_bits(hh);
            *reinterpret_cast<uint32_t*>(Ol + off) = bf2_bits(ll);
        }
    }
}

// ---------------- launch -----------------------------------------------------
extern "C" void kernel_launch(void* const* d_in, const int* in_sizes, int n_in,
                              void* d_out, int out_size) {
    const float* x           = (const float*)d_in[0];
    const int*   attn_mask   = (const int*)  d_in[1];
    const float* w_norm_attn = (const float*)d_in[2];
    const float* wq          = (const float*)d_in[3];
    const float* wk          = (const float*)d_in[4];
    const float* wv          = (const float*)d_in[5];
    const float* wo          = (const float*)d_in[6];
    const float* w_norm_mlp  = (const float*)d_in[7];
    const float* w_up        = (const float*)d_in[8];
    const float* w_down      = (const float*)d_in[9];
    float* out = (float*)d_out;

    bf16 *h_hi, *h_lo, *q_hi, *q_lo, *k_hi, *k_lo, *v_hi, *v_lo;
    bf16 *att_hi, *att_lo, *up_hi, *up_lo;
    bf16 *wq_hi, *wq_lo, *wk_hi, *wk_lo, *wv_hi, *wv_lo, *wo_hi, *wo_lo;
    bf16 *wu_hi, *wu_lo, *wd_hi, *wd_lo;
    float* x1;
    cudaGetSymbolAddress((void**)&h_hi, g_h_hi);   cudaGetSymbolAddress((void**)&h_lo, g_h_lo);
    cudaGetSymbolAddress((void**)&q_hi, g_q_hi);   cudaGetSymbolAddress((void**)&q_lo, g_q_lo);
    cudaGetSymbolAddress((void**)&k_hi, g_k_hi);   cudaGetSymbolAddress((void**)&k_lo, g_k_lo);
    cudaGetSymbolAddress((void**)&v_hi, g_v_hi);   cudaGetSymbolAddress((void**)&v_lo, g_v_lo);
    cudaGetSymbolAddress((void**)&att_hi, g_att_hi); cudaGetSymbolAddress((void**)&att_lo, g_att_lo);
    cudaGetSymbolAddress((void**)&up_hi, g_up_hi); cudaGetSymbolAddress((void**)&up_lo, g_up_lo);
    cudaGetSymbolAddress((void**)&wq_hi, g_wq_hi); cudaGetSymbolAddress((void**)&wq_lo, g_wq_lo);
    cudaGetSymbolAddress((void**)&wk_hi, g_wk_hi); cudaGetSymbolAddress((void**)&wk_lo, g_wk_lo);
    cudaGetSymbolAddress((void**)&wv_hi, g_wv_hi); cudaGetSymbolAddress((void**)&wv_lo, g_wv_lo);
    cudaGetSymbolAddress((void**)&wo_hi, g_wo_hi); cudaGetSymbolAddress((void**)&wo_lo, g_wo_lo);
    cudaGetSymbolAddress((void**)&wu_hi, g_wu_hi); cudaGetSymbolAddress((void**)&wu_lo, g_wu_lo);
    cudaGetSymbolAddress((void**)&wd_hi, g_wd_hi); cudaGetSymbolAddress((void**)&wd_lo, g_wd_lo);
    cudaGetSymbolAddress((void**)&x1, g_x1);

    cudaFuncSetAttribute(flash_attn_tc,
                         cudaFuncAttributeMaxDynamicSharedMemorySize, ATT_SMEM_BYTES);
    cudaFuncSetAttribute(mma_gemm<0>,
                         cudaFuncAttributeMaxDynamicSharedMemorySize, GEMM_SMEM);
    cudaFuncSetAttribute(mma_gemm<1>,
                         cudaFuncAttributeMaxDynamicSharedMemorySize, GEMM_SMEM);
    cudaFuncSetAttribute(mma_gemm<2>,
                         cudaFuncAttributeMaxDynamicSharedMemorySize, GEMM_SMEM);

    // 0) split weights to bf16 hi/lo (2 launches)
    const int DD4 = D_MODEL * D_MODEL / 4;
    const int UD4 = MLP_DIM * D_MODEL / 4;
    split_dd<<<dim3((DD4 + 255) / 256, 4), 256>>>(wq, wk, wv, wo,
        wq_hi, wq_lo, wk_hi, wk_lo, wv_hi, wv_lo, wo_hi, wo_lo);
    split_ud<<<dim3((UD4 + 255) / 256, 2), 256>>>(w_up, w_down,
        wu_hi, wu_lo, wd_hi, wd_lo);

    // 1) rmsnorm(x) -> h (bf16 hi/lo)
    rmsnorm_split<<<TOK, 256>>>(x, w_norm_attn, h_hi, h_lo);

    // 2) q, k, v projections
    dim3 gD(D_MODEL / 128, TOK / 128);
    mma_gemm<0><<<gD, 256, GEMM_SMEM>>>(TOK, D_MODEL, D_MODEL,
        h_hi, h_lo, wq_hi, wq_lo, nullptr, nullptr, q_hi, q_lo);
    mma_gemm<0><<<gD, 256, GEMM_SMEM>>>(TOK, D_MODEL, D_MODEL,
        h_hi, h_lo, wk_hi, wk_lo, nullptr, nullptr, k_hi, k_lo);
    mma_gemm<0><<<gD, 256, GEMM_SMEM>>>(TOK, D_MODEL, D_MODEL,
        h_hi, h_lo, wv_hi, wv_lo, nullptr, nullptr, v_hi, v_lo);  // <- launch #6 (profiled)

    // 3) attention (bf16 split in/out)
    dim3 gA(SEQ / 128, N_HEADS, BATCH);
    flash_attn_tc<<<gA, 256, ATT_SMEM_BYTES>>>(q_hi, q_lo, k_hi, k_lo,
                                               v_hi, v_lo, attn_mask,
                                               att_hi, att_lo);

    // 4) output projection + residual -> x1 (fp32)
    mma_gemm<2><<<gD, 256, GEMM_SMEM>>>(TOK, D_MODEL, D_MODEL,
        att_hi, att_lo, wo_hi, wo_lo, x, x1, nullptr, nullptr);

    // 5) rmsnorm(x1) -> h (bf16 hi/lo)
    rmsnorm_split<<<TOK, 256>>>(x1, w_norm_mlp, h_hi, h_lo);

    // 6) up projection + gelu (split-store)
    dim3 gU(MLP_DIM / 128, TOK / 128);
    mma_gemm<1><<<gU, 256, GEMM_SMEM>>>(TOK, MLP_DIM, D_MODEL,
        h_hi, h_lo, wu_hi, wu_lo, nullptr, nullptr, up_hi, up_lo);

    // 7) down projection + residual -> out (fp32)
    mma_gemm<2><<<gD, 256, GEMM_SMEM>>>(TOK, D_MODEL, MLP_DIM,
        up_hi, up_lo, wd_hi, wd_lo, x1, out, nullptr, nullptr);
}

// round 7
// speedup vs baseline: 1.1863x; 1.0272x over previous
#include <cuda_runtime.h>
#include <cuda_bf16.h>
#include <math.h>
#include <stdint.h>

#define D_MODEL 2048
#define N_HEADS 16
#define HEAD_DIM 128
#define MLP_DIM 8192
#define BATCH 2
#define SEQ 2048
#define TOK (BATCH * SEQ)

typedef __nv_bfloat16 bf16;

// ---------------- scratch (static device globals) ---------------------------
__device__ bf16 g_h_hi[(size_t)TOK * D_MODEL],  g_h_lo[(size_t)TOK * D_MODEL];
__device__ bf16 g_q_hi[(size_t)TOK * D_MODEL],  g_q_lo[(size_t)TOK * D_MODEL];
__device__ bf16 g_k_hi[(size_t)TOK * D_MODEL],  g_k_lo[(size_t)TOK * D_MODEL];
__device__ bf16 g_v_hi[(size_t)TOK * D_MODEL],  g_v_lo[(size_t)TOK * D_MODEL];
__device__ bf16 g_att_hi[(size_t)TOK * D_MODEL], g_att_lo[(size_t)TOK * D_MODEL];
__device__ bf16 g_up_hi[(size_t)TOK * MLP_DIM], g_up_lo[(size_t)TOK * MLP_DIM];
__device__ bf16 g_wq_hi[(size_t)D_MODEL * D_MODEL], g_wq_lo[(size_t)D_MODEL * D_MODEL];
__device__ bf16 g_wk_hi[(size_t)D_MODEL * D_MODEL], g_wk_lo[(size_t)D_MODEL * D_MODEL];
__device__ bf16 g_wv_hi[(size_t)D_MODEL * D_MODEL], g_wv_lo[(size_t)D_MODEL * D_MODEL];
__device__ bf16 g_wo_hi[(size_t)D_MODEL * D_MODEL], g_wo_lo[(size_t)D_MODEL * D_MODEL];
__device__ bf16 g_wu_hi[(size_t)MLP_DIM * D_MODEL], g_wu_lo[(size_t)MLP_DIM * D_MODEL];
__device__ bf16 g_wd_hi[(size_t)D_MODEL * MLP_DIM], g_wd_lo[(size_t)D_MODEL * MLP_DIM];
__device__ float g_x1[(size_t)TOK * D_MODEL];

// ================= PTX helpers (baseline PTX, sm_80+) =======================
__device__ __forceinline__ uint32_t smem_to_u32(const void* p) {
    uint32_t a;
    asm("{ .reg .u64 t; cvta.to.shared.u64 t, %1; cvt.u32.u64 %0, t; }"
        : "=r"(a) : "l"(p));
    return a;
}
__device__ __forceinline__ void ldsm_x4(uint32_t addr, uint32_t* r) {
    asm volatile("ldmatrix.sync.aligned.m8n8.x4.shared.b16 {%0,%1,%2,%3}, [%4];"
                 : "=r"(r[0]), "=r"(r[1]), "=r"(r[2]), "=r"(r[3]) : "r"(addr));
}
__device__ __forceinline__ void mma_bf16(float* d, const uint32_t* a,
                                         const uint32_t* b) {
    asm volatile(
        "mma.sync.aligned.m16n8k16.row.col.f32.bf16.bf16.f32 "
        "{%0,%1,%2,%3}, {%4,%5,%6,%7}, {%8,%9}, {%0,%1,%2,%3};"
        : "+f"(d[0]), "+f"(d[1]), "+f"(d[2]), "+f"(d[3])
        : "r"(a[0]), "r"(a[1]), "r"(a[2]), "r"(a[3]), "r"(b[0]), "r"(b[1]));
}
__device__ __forceinline__ uint32_t bf2_bits(__nv_bfloat162 v) {
    return *reinterpret_cast<uint32_t*>(&v);
}
#define CP16(dst, src) \
    asm volatile("cp.async.cg.shared.global [%0], [%1], 16;" \
                 :: "r"(dst), "l"(src) : "memory")
#define CPCOMMIT() asm volatile("cp.async.commit_group;" ::: "memory")
#define CPWAIT(n)  asm volatile("cp.async.wait_group %0;" :: "n"(n) : "memory")

// ================= fp32 -> bf16 hi/lo split (weights; 2 launches) ===========
__device__ __forceinline__ void split_store(const float* src, bf16* hi, bf16* lo,
                                            int i) {
    float4 v = reinterpret_cast<const float4*>(src)[i];
    __nv_bfloat162 h01 = __floats2bfloat162_rn(v.x, v.y);
    __nv_bfloat162 h23 = __floats2bfloat162_rn(v.z, v.w);
    __nv_bfloat162 l01 = __floats2bfloat162_rn(v.x - __bfloat162float(h01.x),
                                               v.y - __bfloat162float(h01.y));
    __nv_bfloat162 l23 = __floats2bfloat162_rn(v.z - __bfloat162float(h23.x),
                                               v.w - __bfloat162float(h23.y));
    reinterpret_cast<uint2*>(hi)[i] = make_uint2(bf2_bits(h01), bf2_bits(h23));
    reinterpret_cast<uint2*>(lo)[i] = make_uint2(bf2_bits(l01), bf2_bits(l23));
}

__global__ void split_dd(const float* __restrict__ wq, const float* __restrict__ wk,
                         const float* __restrict__ wv, const float* __restrict__ wo,
                         bf16* qh, bf16* ql, bf16* kh, bf16* kl,
                         bf16* vh, bf16* vl, bf16* oh, bf16* ol) {
    int i = blockIdx.x * blockDim.x + threadIdx.x;
    if (i >= D_MODEL * D_MODEL / 4) return;
    switch (blockIdx.y) {
        case 0: split_store(wq, qh, ql, i); break;
        case 1: split_store(wk, kh, kl, i); break;
        case 2: split_store(wv, vh, vl, i); break;
        default: split_store(wo, oh, ol, i); break;
    }
}
__global__ void split_ud(const float* __restrict__ wu, const float* __restrict__ wd,
                         bf16* uh, bf16* ul, bf16* dh, bf16* dl) {
    int i = blockIdx.x * blockDim.x + threadIdx.x;
    if (i >= MLP_DIM * D_MODEL / 4) return;
    if (blockIdx.y == 0) split_store(wu, uh, ul, i);
    else                 split_store(wd, dh, dl, i);
}

// ================= RMSNorm -> bf16 hi/lo =====================================
__global__ void rmsnorm_split(const float* __restrict__ x,
                              const float* __restrict__ w,
                              bf16* __restrict__ hi, bf16* __restrict__ lo) {
    int row = blockIdx.x;
    const float4* xr = reinterpret_cast<const float4*>(x + (size_t)row * D_MODEL);
    const float4* w4 = reinterpret_cast<const float4*>(w);

    float ss = 0.f;
    for (int i = threadIdx.x; i < D_MODEL / 4; i += blockDim.x) {
        float4 v = xr[i];
        ss += v.x * v.x + v.y * v.y + v.z * v.z + v.w * v.w;
    }
    for (int off = 16; off > 0; off >>= 1)
        ss += __shfl_xor_sync(0xFFFFFFFFu, ss, off);
    __shared__ float red[8];
    __shared__ float s_rms;
    int lane = threadIdx.x & 31, wid = threadIdx.x >> 5;
    if (lane == 0) red[wid] = ss;
    __syncthreads();
    if (threadIdx.x == 0) {
        float tt = 0.f;
        #pragma unroll
        for (int i = 0; i < 8; i++) tt += red[i];
        s_rms = rsqrtf(tt / (float)D_MODEL + 1e-6f);
    }
    __syncthreads();
    float r = s_rms;
    uint2* h2 = reinterpret_cast<uint2*>(hi + (size_t)row * D_MODEL);
    uint2* l2 = reinterpret_cast<uint2*>(lo + (size_t)row * D_MODEL);
    for (int i = threadIdx.x; i < D_MODEL / 4; i += blockDim.x) {
        float4 v = xr[i];
        float4 ww = w4[i];
        float y0 = v.x * r * ww.x, y1 = v.y * r * ww.y;
        float y2 = v.z * r * ww.z, y3 = v.w * r * ww.w;
        __nv_bfloat162 h01 = __floats2bfloat162_rn(y0, y1);
        __nv_bfloat162 h23 = __floats2bfloat162_rn(y2, y3);
        __nv_bfloat162 l01 = __floats2bfloat162_rn(y0 - __bfloat162float(h01.x),
                                                   y1 - __bfloat162float(h01.y));
        __nv_bfloat162 l23 = __floats2bfloat162_rn(y2 - __bfloat162float(h23.x),
                                                   y3 - __bfloat162float(h23.y));
        h2[i] = make_uint2(bf2_bits(h01), bf2_bits(h23));
        l2[i] = make_uint2(bf2_bits(l01), bf2_bits(l23));
    }
}

// ================= bf16-split GEMM: 128x256 CTA tile, 64x64 warp tile ========
// C = A @ B^T with A = Ah+Al, B = Bh+Bl; acc += Ah*Bh + Ah*Bl + Al*Bh.
// EPI: 0 = split-store bf16 hi/lo, 1 = gelu + split-store, 2 = residual fp32
#define KC 32
#define ROWB 128
#define A_TILE (128 * ROWB)            // 16 KB
#define B_TILE (256 * ROWB)            // 32 KB
#define STAGE_B (A_TILE + B_TILE)      // 48 KB
#define NSTAGE 4
#define GEMM_SMEM (NSTAGE * STAGE_B)   // 192 KB

template <int EPI>
__global__ void __launch_bounds__(256, 1)
mma_gemm(int M, int N, int K,
         const bf16* __restrict__ Ah_, const bf16* __restrict__ Al_,
         const bf16* __restrict__ Bh_, const bf16* __restrict__ Bl_,
         const float* __restrict__ RES, float* __restrict__ Cf,
         bf16* __restrict__ Ch, bf16* __restrict__ Cl) {
    extern __shared__ char smem[];
    const uint32_t su = smem_to_u32(smem);

    const int t = threadIdx.x;
    const int lane = t & 31;
    const int wid = t >> 5;
    const int wm = wid & 1;        // 2 m-warps  -> 64 rows each
    const int wn = wid >> 1;       // 4 n-warps  -> 64 cols each
    const int m0 = blockIdx.y * 128;
    const int n0 = blockIdx.x * 256;

    // ---- staging: A 2 threads/row (hi|lo halves), B 1 thread/row (both) ----
    const int arow = t >> 1;
    const int ahalf = t & 1;
    const bf16* Asrc = (ahalf ? Al_ : Ah_) + (size_t)(m0 + arow) * K;
    const uint32_t asw = ((uint32_t)(arow & 7)) << 4;
    const uint32_t adst = (uint32_t)arow * ROWB;

    const int brow = t;
    const bf16* Bhsrc = Bh_ + (size_t)(n0 + brow) * K;
    const bf16* Blsrc = Bl_ + (size_t)(n0 + brow) * K;
    const uint32_t bsw = ((uint32_t)(brow & 7)) << 4;
    const uint32_t bdst = (uint32_t)brow * ROWB;

    auto CP_chunk = [&](int s, int k0) {
        const uint32_t stA = su + (uint32_t)s * STAGE_B;
        const uint32_t stB = stA + A_TILE;
        #pragma unroll
        for (int c = 0; c < 4; c++) {
            CP16(stA + adst + (((uint32_t)(ahalf * 64 + c * 16)) ^ asw),
                 Asrc + k0 + c * 8);
        }
        #pragma unroll
        for (int c = 0; c < 4; c++) {
            CP16(stB + bdst + (((uint32_t)(c * 16)) ^ bsw), Bhsrc + k0 + c * 8);
            CP16(stB + bdst + (((uint32_t)(64 + c * 16)) ^ bsw), Blsrc + k0 + c * 8);
        }
    };

    float acc[4][8][4];
    #pragma unroll
    for (int mt = 0; mt < 4; mt++)
        #pragma unroll
        for (int nt = 0; nt < 8; nt++)
            #pragma unroll
            for (int j = 0; j < 4; j++) acc[mt][nt][j] = 0.f;

    const int nch = K / KC;
    #pragma unroll
    for (int s = 0; s < NSTAGE - 1; s++) {
        CP_chunk(s, s * KC);
        CPCOMMIT();
    }

    const int lrow16 = lane & 15;
    const int cg = (lane >> 4) & 1;

    for (int i = 0; i < nch; i++) {
        CPWAIT(NSTAGE - 2);
        __syncthreads();

        const uint32_t sA = su + (uint32_t)(i % NSTAGE) * STAGE_B;
        const uint32_t sB = sA + A_TILE;

        #pragma unroll
        for (int ks = 0; ks < 2; ks++) {
            const uint32_t cbh = (uint32_t)(ks * 32 + cg * 16);
            uint32_t Ahf[4][4], Alf[4][4];
            #pragma unroll
            for (int mt = 0; mt < 4; mt++) {
                const int row = wm * 64 + mt * 16 + lrow16;
                const uint32_t swz = (uint32_t)(row & 7) << 4;
                const uint32_t base = sA + (uint32_t)row * ROWB;
                ldsm_x4(base + (cbh ^ swz), Ahf[mt]);
                ldsm_x4(base + ((cbh + 64) ^ swz), Alf[mt]);
            }
            #pragma unroll
            for (int q = 0; q < 4; q++) {
                const int row = wn * 64 + q * 16 + lrow16;
                const uint32_t swz = (uint32_t)(row & 7) << 4;
                const uint32_t base = sB + (uint32_t)row * ROWB;
                uint32_t rh[4], rl[4];
                ldsm_x4(base + (cbh ^ swz), rh);
                ldsm_x4(base + ((cbh + 64) ^ swz), rl);
                uint32_t bh0[2] = {rh[0], rh[2]};
                uint32_t bh1[2] = {rh[1], rh[3]};
                uint32_t bl0[2] = {rl[0], rl[2]};
                uint32_t bl1[2] = {rl[1], rl[3]};
                #pragma unroll
                for (int mt = 0; mt < 4; mt++) {
                    mma_bf16(acc[mt][2 * q + 0], Ahf[mt], bh0);
                    mma_bf16(acc[mt][2 * q + 0], Ahf[mt], bl0);
                    mma_bf16(acc[mt][2 * q + 0], Alf[mt], bh0);
                    mma_bf16(acc[mt][2 * q + 1], Ahf[mt], bh1);
                    mma_bf16(acc[mt][2 * q + 1], Ahf[mt], bl1);
                    mma_bf16(acc[mt][2 * q + 1], Alf[mt], bh1);
                }
            }
        }

        if (i + NSTAGE - 1 < nch) {
            CP_chunk((i + NSTAGE - 1) % NSTAGE, (i + NSTAGE - 1) * KC);
        }
        CPCOMMIT();
    }

    // ---- epilogue ----
    const int er0 = m0 + wm * 64 + (lane >> 2);
    const int ec0 = n0 + wn * 64 + (lane & 3) * 2;
    #pragma unroll
    for (int mt = 0; mt < 4; mt++) {
        #pragma unroll
        for (int g = 0; g < 2; g++) {
            const int row = er0 + mt * 16 + g * 8;
            #pragma unroll
            for (int nt = 0; nt < 8; nt++) {
                const int col = ec0 + nt * 8;
                float v0 = acc[mt][nt][g * 2 + 0];
                float v1 = acc[mt][nt][g * 2 + 1];
                size_t roff = (size_t)row * N + col;
                if (EPI == 2) {
                    float2 r = *reinterpret_cast<const float2*>(RES + roff);
                    *reinterpret_cast<float2*>(Cf + roff) =
                        make_float2(v0 + r.x, v1 + r.y);
                } else {
                    if (EPI == 1) {
                        v0 = 0.5f * v0 * (1.0f + erff(v0 * 0.70710678118654752f));
                        v1 = 0.5f * v1 * (1.0f + erff(v1 * 0.70710678118654752f));
                    }
                    __nv_bfloat162 hh = __floats2bfloat162_rn(v0, v1);
                    __nv_bfloat162 ll = __floats2bfloat162_rn(
                        v0 - __bfloat162float(hh.x), v1 - __bfloat162float(hh.y));
                    *reinterpret_cast<uint32_t*>(Ch + roff) = bf2_bits(hh);
                    *reinterpret_cast<uint32_t*>(Cl + roff) = bf2_bits(ll);
                }
            }
        }
    }
}

// ================= tensor-core flash attention (bf16 split inputs) ===========
#define ATT_BUF0 65536
#define ATT_MASK 131072
#define ATT_SMEM_BYTES (131072 + 512)

__device__ __forceinline__ void att_stage_chunk(
    char* smem, uint32_t sb, uint32_t bufoff,
    const bf16* __restrict__ Kh, const bf16* __restrict__ Kl,
    const bf16* __restrict__ Vh, const bf16* __restrict__ Vl,
    const int* __restrict__ bm, int kv0, int slot, int t) {
    {
        const int row = t >> 2;
        const int dq = (t & 3) * 32;
        const size_t goff = (size_t)(kv0 + row) * D_MODEL + dq;
        const uint32_t rbase = sb + bufoff + (uint32_t)row * 256;
        const uint32_t swr = (uint32_t)(row & 7) << 4;
        #pragma unroll
        for (int i = 0; i < 4; i++) {
            const uint32_t off = ((uint32_t)(dq * 2 + i * 16)) ^ swr;
            CP16(rbase + off, Kh + goff + i * 8);
            CP16(rbase + 16384 + off, Kl + goff + i * 8);
        }
    }
    {
        const int kvp = t & 31;
        const int dblk = t >> 5;
        const size_t r0 = (size_t)(kv0 + 2 * kvp) * D_MODEL + dblk * 16;
        const size_t r1 = r0 + D_MODEL;
        uint4 h0a = *reinterpret_cast<const uint4*>(Vh + r0);
        uint4 h0b = *reinterpret_cast<const uint4*>(Vh + r0 + 8);
        uint4 h1a = *reinterpret_cast<const uint4*>(Vh + r1);
        uint4 h1b = *reinterpret_cast<const uint4*>(Vh + r1 + 8);
        uint4 l0a = *reinterpret_cast<const uint4*>(Vl + r0);
        uint4 l0b = *reinterpret_cast<const uint4*>(Vl + r0 + 8);
        uint4 l1a = *reinterpret_cast<const uint4*>(Vl + r1);
        uint4 l1b = *reinterpret_cast<const uint4*>(Vl + r1 + 8);
        uint32_t h0[8] = {h0a.x, h0a.y, h0a.z, h0a.w, h0b.x, h0b.y, h0b.z, h0b.w};
        uint32_t h1[8] = {h1a.x, h1a.y, h1a.z, h1a.w, h1b.x, h1b.y, h1b.z, h1b.w};
        uint32_t l0[8] = {l0a.x, l0a.y, l0a.z, l0a.w, l0b.x, l0b.y, l0b.z, l0b.w};
        uint32_t l1[8] = {l1a.x, l1a.y, l1a.z, l1a.w, l1b.x, l1b.y, l1b.z, l1b.w};
        const uint32_t koff = (uint32_t)(kvp * 4);
        #pragma unroll
        for (int dd = 0; dd < 8; dd++) {
            const int d0 = dblk * 16 + dd * 2;
            const uint32_t vb0 = sb + bufoff + 32768 + (uint32_t)d0 * 128 +
                                 (koff ^ ((uint32_t)(d0 & 7) << 4));
            const uint32_t vb1 = sb + bufoff + 32768 + (uint32_t)(d0 + 1) * 128 +
                                 (koff ^ ((uint32_t)((d0 + 1) & 7) << 4));
            asm volatile("st.shared.b32 [%0], %1;" :: "r"(vb0),
                         "r"(__byte_perm(h0[dd], h1[dd], 0x5410)) : "memory");
            asm volatile("st.shared.b32 [%0], %1;" :: "r"(vb1),
                         "r"(__byte_perm(h0[dd], h1[dd], 0x7632)) : "memory");
            asm volatile("st.shared.b32 [%0], %1;" :: "r"(vb0 + 16384),
                         "r"(__byte_perm(l0[dd], l1[dd], 0x5410)) : "memory");
            asm volatile("st.shared.b32 [%0], %1;" :: "r"(vb1 + 16384),
                         "r"(__byte_perm(l0[dd], l1[dd], 0x7632)) : "memory");
        }
    }
    if (t < 64)
        reinterpret_cast<int*>(smem + ATT_MASK + slot * 256)[t] = bm[kv0 + t];
}

__global__ void __launch_bounds__(256, 1)
flash_attn_tc(const bf16* __restrict__ Qh, const bf16* __restrict__ Ql,
              const bf16* __restrict__ Kh, const bf16* __restrict__ Kl,
              const bf16* __restrict__ Vh, const bf16* __restrict__ Vl,
              const int* __restrict__ mask,
              bf16* __restrict__ Oh, bf16* __restrict__ Ol) {
    extern __shared__ char smem[];
    const uint32_t sb = smem_to_u32(smem);
    const int t = threadIdx.x, lane = t & 31, w = t >> 5;
    const int qi = gridDim.x - 1 - blockIdx.x;
    const int h = blockIdx.y, b = blockIdx.z;
    const int q0 = qi * 128;
    const size_t base = (size_t)b * SEQ * D_MODEL + (size_t)h * HEAD_DIM;
    const int* bm = mask + b * SEQ;
    const float scale = 0.08838834764831845f;

    {
        const int row = t >> 1, half = t & 1;
        const size_t goff = base + (size_t)(q0 + row) * D_MODEL + half * 64;
        const uint4* ghv = reinterpret_cast<const uint4*>(Qh + goff);
        const uint4* glv = reinterpret_cast<const uint4*>(Ql + goff);
        char* qr = smem + (uint32_t)row * 256;
        const uint32_t swr = (uint32_t)(row & 7) << 4;
        #pragma unroll
        for (int i = 0; i < 8; i++) {
            const uint32_t off = ((uint32_t)(half * 128 + i * 16)) ^ swr;
            *reinterpret_cast<uint4*>(qr + off) = ghv[i];
            *reinterpret_cast<uint4*>(qr + 32768 + off) = glv[i];
        }
    }
    att_stage_chunk(smem, sb, ATT_BUF0, Kh + base, Kl + base,
                    Vh + base, Vl + base, bm, 0, 0, t);
    CPCOMMIT();
    CPWAIT(0);
    __syncthreads();

    uint32_t Aqh[8][4], Aql[8][4];
    {
        const int r = w * 16 + (lane & 15);
        const uint32_t swz = (uint32_t)(r & 7) << 4;
        const uint32_t cgo = ((uint32_t)(lane >> 4)) << 4;
        const uint32_t qb = sb + (uint32_t)r * 256;
        #pragma unroll
        for (int ds = 0; ds < 8; ds++) {
            const uint32_t off = (((uint32_t)(ds * 32)) + cgo) ^ swz;
            ldsm_x4(qb + off, Aqh[ds]);
            ldsm_x4(qb + 32768 + off, Aql[ds]);
        }
    }
    __syncthreads();

    float m1 = -1e30f, l1 = 0.f, m2 = -1e30f, l2 = 0.f;
    float acc[16][4];
    #pragma unroll
    for (int nt = 0; nt < 16; nt++)
        #pragma unroll
        for (int c = 0; c < 4; c++) acc[nt][c] = 0.f;

    const int r1g = q0 + w * 16 + (lane >> 2);
    const int r2g = r1g + 8;
    const int nch = 2 * qi + 2;
    const uint32_t cgo = ((uint32_t)(lane >> 4)) << 4;

    for (int j = 0; j < nch; j++) {
        const int s = j & 1;
        const uint32_t bufo = s ? 0u : (uint32_t)ATT_BUF0;
        const int kv0 = j * 64;

        if (j + 1 < nch) {
            att_stage_chunk(smem, sb, s ? (uint32_t)ATT_BUF0 : 0u,
                            Kh + base, Kl + base, Vh + base, Vl + base,
                            bm, kv0 + 64, (j + 1) & 1, t);
            CPCOMMIT();
        }

        float sacc[8][4];
        #pragma unroll
        for (int nt = 0; nt < 8; nt++)
            #pragma unroll
            for (int c = 0; c < 4; c++) sacc[nt][c] = 0.f;

        #pragma unroll
        for (int g4 = 0; g4 < 4; g4++) {
            const int kr = g4 * 16 + (lane & 15);
            const uint32_t swz = (uint32_t)(kr & 7) << 4;
            const uint32_t kb = sb + bufo + (uint32_t)kr * 256;
            #pragma unroll
            for (int ds = 0; ds < 8; ds++) {
                const uint32_t off = (((uint32_t)(ds * 32)) + cgo) ^ swz;
                uint32_t rh[4], rl[4];
                ldsm_x4(kb + off, rh);
                ldsm_x4(kb + 16384 + off, rl);
                uint32_t bh0[2] = {rh[0], rh[2]}, bh1[2] = {rh[1], rh[3]};
                uint32_t bl0[2] = {rl[0], rl[2]}, bl1[2] = {rl[1], rl[3]};
                mma_bf16(sacc[2 * g4 + 0], Aqh[ds], bh0);
                mma_bf16(sacc[2 * g4 + 0], Aqh[ds], bl0);
                mma_bf16(sacc[2 * g4 + 0], Aql[ds], bh0);
                mma_bf16(sacc[2 * g4 + 1], Aqh[ds], bh1);
                mma_bf16(sacc[2 * g4 + 1], Aqh[ds], bl1);
                mma_bf16(sacc[2 * g4 + 1], Aql[ds], bh1);
            }
        }

        const int* mrow = reinterpret_cast<const int*>(smem + ATT_MASK + s * 256);
        #pragma unroll
        for (int nt = 0; nt < 8; nt++) {
            const int c0 = nt * 8 + (lane & 3) * 2;
            const int k0g = kv0 + c0, k1g = k0g + 1;
            const bool mv0 = mrow[c0] != 0, mv1 = mrow[c0 + 1] != 0;
            float v0 = sacc[nt][0] * scale, v1 = sacc[nt][1] * scale;
            float v2 = sacc[nt][2] * scale, v3 = sacc[nt][3] * scale;
            sacc[nt][0] = (k0g > r1g || !mv0) ? -1e9f : v0;
            sacc[nt][1] = (k1g > r1g || !mv1) ? -1e9f : v1;
            sacc[nt][2] = (k0g > r2g || !mv0) ? -1e9f : v2;
            sacc[nt][3] = (k1g > r2g || !mv1) ? -1e9f : v3;
        }

        float mx1 = -1e30f, mx2 = -1e30f;
        #pragma unroll
        for (int nt = 0; nt < 8; nt++) {
            mx1 = fmaxf(mx1, fmaxf(sacc[nt][0], sacc[nt][1]));
            mx2 = fmaxf(mx2, fmaxf(sacc[nt][2], sacc[nt][3]));
        }
        mx1 = fmaxf(mx1, __shfl_xor_sync(0xFFFFFFFFu, mx1, 1));
        mx1 = fmaxf(mx1, __shfl_xor_sync(0xFFFFFFFFu, mx1, 2));
        mx2 = fmaxf(mx2, __shfl_xor_sync(0xFFFFFFFFu, mx2, 1));
        mx2 = fmaxf(mx2, __shfl_xor_sync(0xFFFFFFFFu, mx2, 2));
        const float m1n = fmaxf(m1, mx1), m2n = fmaxf(m2, mx2);
        const float a1 = __expf(m1 - m1n), a2 = __expf(m2 - m2n);
        float s1 = 0.f, s2 = 0.f;
        #pragma unroll
        for (int nt = 0; nt < 8; nt++) {
            sacc[nt][0] = __expf(sacc[nt][0] - m1n);
            sacc[nt][1] = __expf(sacc[nt][1] - m1n);
            sacc[nt][2] = __expf(sacc[nt][2] - m2n);
            sacc[nt][3] = __expf(sacc[nt][3] - m2n);
            s1 += sacc[nt][0] + sacc[nt][1];
            s2 += sacc[nt][2] + sacc[nt][3];
        }
        s1 += __shfl_xor_sync(0xFFFFFFFFu, s1, 1);
        s1 += __shfl_xor_sync(0xFFFFFFFFu, s1, 2);
        s2 += __shfl_xor_sync(0xFFFFFFFFu, s2, 1);
        s2 += __shfl_xor_sync(0xFFFFFFFFu, s2, 2);
        l1 = l1 * a1 + s1; m1 = m1n;
        l2 = l2 * a2 + s2; m2 = m2n;
        #pragma unroll
        for (int nt = 0; nt < 16; nt++) {
            acc[nt][0] *= a1; acc[nt][1] *= a1;
            acc[nt][2] *= a2; acc[nt][3] *= a2;
        }

        #pragma unroll
        for (int ks = 0; ks < 4; ks++) {
            const float* p0 = sacc[2 * ks];
            const float* p1 = sacc[2 * ks + 1];
            __nv_bfloat162 h0 = __floats2bfloat162_rn(p0[0], p0[1]);
            __nv_bfloat162 h1 = __floats2bfloat162_rn(p0[2], p0[3]);
            __nv_bfloat162 h2 = __floats2bfloat162_rn(p1[0], p1[1]);
            __nv_bfloat162 h3 = __floats2bfloat162_rn(p1[2], p1[3]);
            uint32_t pa_h[4] = {bf2_bits(h0), bf2_bits(h1), bf2_bits(h2), bf2_bits(h3)};
            __nv_bfloat162 e0 = __floats2bfloat162_rn(
                p0[0] - __bfloat162float(h0.x), p0[1] - __bfloat162float(h0.y));
            __nv_bfloat162 e1 = __floats2bfloat162_rn(
                p0[2] - __bfloat162float(h1.x), p0[3] - __bfloat162float(h1.y));
            __nv_bfloat162 e2 = __floats2bfloat162_rn(
                p1[0] - __bfloat162float(h2.x), p1[1] - __bfloat162float(h2.y));
            __nv_bfloat162 e3 = __floats2bfloat162_rn(
                p1[2] - __bfloat162float(h3.x), p1[3] - __bfloat162float(h3.y));
            uint32_t pa_l[4] = {bf2_bits(e0), bf2_bits(e1), bf2_bits(e2), bf2_bits(e3)};

            #pragma unroll
            for (int gd = 0; gd < 8; gd++) {
                const int dr = gd * 16 + (lane & 15);
                const uint32_t swz = (uint32_t)(dr & 7) << 4;
                const uint32_t off = (((uint32_t)(ks * 32)) + cgo) ^ swz;
                const uint32_t vb = sb + bufo + 32768 + (uint32_t)dr * 128;
                uint32_t rh[4], rl[4];
                ldsm_x4(vb + off, rh);
                ldsm_x4(vb + 16384 + off, rl);
                uint32_t bh0[2] = {rh[0], rh[2]}, bh1[2] = {rh[1], rh[3]};
                uint32_t bl0[2] = {rl[0], rl[2]}, bl1[2] = {rl[1], rl[3]};
                mma_bf16(acc[2 * gd + 0], pa_h, bh0);
                mma_bf16(acc[2 * gd + 0], pa_h, bl0);
                mma_bf16(acc[2 * gd + 0], pa_l, bh0);
                mma_bf16(acc[2 * gd + 1], pa_h, bh1);
                mma_bf16(acc[2 * gd + 1], pa_h, bl1);
                mma_bf16(acc[2 * gd + 1], pa_l, bh1);
            }
        }

        CPWAIT(0);
        __syncthreads();
    }

    const float i1 = (l1 > 0.f) ? 1.f / l1 : 0.f;
    const float i2 = (l2 > 0.f) ? 1.f / l2 : 0.f;
    #pragma unroll
    for (int nt = 0; nt < 16; nt++) {
        const int col = nt * 8 + (lane & 3) * 2;
        {
            float o0 = acc[nt][0] * i1, o1 = acc[nt][1] * i1;
            __nv_bfloat162 hh = __floats2bfloat162_rn(o0, o1);
            __nv_bfloat162 ll = __floats2bfloat162_rn(
                o0 - __bfloat162float(hh.x), o1 - __bfloat162float(hh.y));
            size_t off = base + (size_t)r1g * D_MODEL + col;
            *reinterpret_cast<uint32_t*>(Oh + off) = bf2_bits(hh);
            *reinterpret_cast<uint32_t*>(Ol + off) = bf2_bits(ll);
        }
        {
            float o0 = acc[nt][2] * i2, o1 = acc[nt][3] * i2;
            __nv_bfloat162 hh = __floats2bfloat162_rn(o0, o1);
            __nv_bfloat162 ll = __floats2bfloat162_rn(
                o0 - __bfloat162float(hh.x), o1 - __bfloat162float(hh.y));
            size_t off = base + (size_t)r2g * D_MODEL + col;
            *reinterpret_cast<uint32_t*>(Oh + off) = bf2_bits(hh);
            *reinterpret_cast<uint32_t*>(Ol + off) = bf2_bits(ll);
        }
    }
}

// ---------------- launch -----------------------------------------------------
extern "C" void kernel_launch(void* const* d_in, const int* in_sizes, int n_in,
                              void* d_out, int out_size) {
    const float* x           = (const float*)d_in[0];
    const int*   attn_mask   = (const int*)  d_in[1];
    const float* w_norm_attn = (const float*)d_in[2];
    const float* wq          = (const float*)d_in[3];
    const float* wk          = (const float*)d_in[4];
    const float* wv          = (const float*)d_in[5];
    const float* wo          = (const float*)d_in[6];
    const float* w_norm_mlp  = (const float*)d_in[7];
    const float* w_up        = (const float*)d_in[8];
    const float* w_down      = (const float*)d_in[9];
    float* out = (float*)d_out;

    bf16 *h_hi, *h_lo, *q_hi, *q_lo, *k_hi, *k_lo, *v_hi, *v_lo;
    bf16 *att_hi, *att_lo, *up_hi, *up_lo;
    bf16 *wq_hi, *wq_lo, *wk_hi, *wk_lo, *wv_hi, *wv_lo, *wo_hi, *wo_lo;
    bf16 *wu_hi, *wu_lo, *wd_hi, *wd_lo;
    float* x1;
    cudaGetSymbolAddress((void**)&h_hi, g_h_hi);   cudaGetSymbolAddress((void**)&h_lo, g_h_lo);
    cudaGetSymbolAddress((void**)&q_hi, g_q_hi);   cudaGetSymbolAddress((void**)&q_lo, g_q_lo);
    cudaGetSymbolAddress((void**)&k_hi, g_k_hi);   cudaGetSymbolAddress((void**)&k_lo, g_k_lo);
    cudaGetSymbolAddress((void**)&v_hi, g_v_hi);   cudaGetSymbolAddress((void**)&v_lo, g_v_lo);
    cudaGetSymbolAddress((void**)&att_hi, g_att_hi); cudaGetSymbolAddress((void**)&att_lo, g_att_lo);
    cudaGetSymbolAddress((void**)&up_hi, g_up_hi); cudaGetSymbolAddress((void**)&up_lo, g_up_lo);
    cudaGetSymbolAddress((void**)&wq_hi, g_wq_hi); cudaGetSymbolAddress((void**)&wq_lo, g_wq_lo);
    cudaGetSymbolAddress((void**)&wk_hi, g_wk_hi); cudaGetSymbolAddress((void**)&wk_lo, g_wk_lo);
    cudaGetSymbolAddress((void**)&wv_hi, g_wv_hi); cudaGetSymbolAddress((void**)&wv_lo, g_wv_lo);
    cudaGetSymbolAddress((void**)&wo_hi, g_wo_hi); cudaGetSymbolAddress((void**)&wo_lo, g_wo_lo);
    cudaGetSymbolAddress((void**)&wu_hi, g_wu_hi); cudaGetSymbolAddress((void**)&wu_lo, g_wu_lo);
    cudaGetSymbolAddress((void**)&wd_hi, g_wd_hi); cudaGetSymbolAddress((void**)&wd_lo, g_wd_lo);
    cudaGetSymbolAddress((void**)&x1, g_x1);

    cudaFuncSetAttribute(flash_attn_tc,
                         cudaFuncAttributeMaxDynamicSharedMemorySize, ATT_SMEM_BYTES);
    cudaFuncSetAttribute(mma_gemm<0>,
                         cudaFuncAttributeMaxDynamicSharedMemorySize, GEMM_SMEM);
    cudaFuncSetAttribute(mma_gemm<1>,
                         cudaFuncAttributeMaxDynamicSharedMemorySize, GEMM_SMEM);
    cudaFuncSetAttribute(mma_gemm<2>,
                         cudaFuncAttributeMaxDynamicSharedMemorySize, GEMM_SMEM);

    // 0) split weights to bf16 hi/lo
    const int DD4 = D_MODEL * D_MODEL / 4;
    const int UD4 = MLP_DIM * D_MODEL / 4;
    split_dd<<<dim3((DD4 + 255) / 256, 4), 256>>>(wq, wk, wv, wo,
        wq_hi, wq_lo, wk_hi, wk_lo, wv_hi, wv_lo, wo_hi, wo_lo);
    split_ud<<<dim3((UD4 + 255) / 256, 2), 256>>>(w_up, w_down,
        wu_hi, wu_lo, wd_hi, wd_lo);

    // 1) rmsnorm(x) -> h (bf16 hi/lo)
    rmsnorm_split<<<TOK, 256>>>(x, w_norm_attn, h_hi, h_lo);

    // 2) q, k, v projections
    dim3 gD(D_MODEL / 256, TOK / 128);
    mma_gemm<0><<<gD, 256, GEMM_SMEM>>>(TOK, D_MODEL, D_MODEL,
        h_hi, h_lo, wq_hi, wq_lo, nullptr, nullptr, q_hi, q_lo);
    mma_gemm<0><<<gD, 256, GEMM_SMEM>>>(TOK, D_MODEL, D_MODEL,
        h_hi, h_lo, wk_hi, wk_lo, nullptr, nullptr, k_hi, k_lo);
    mma_gemm<0><<<gD, 256, GEMM_SMEM>>>(TOK, D_MODEL, D_MODEL,
        h_hi, h_lo, wv_hi, wv_lo, nullptr, nullptr, v_hi, v_lo);  // launch #6 (profiled)

    // 3) attention (bf16 split in/out)
    dim3 gA(SEQ / 128, N_HEADS, BATCH);
    flash_attn_tc<<<gA, 256, ATT_SMEM_BYTES>>>(q_hi, q_lo, k_hi, k_lo,
                                               v_hi, v_lo, attn_mask,
                                               att_hi, att_lo);

    // 4) output projection + residual -> x1 (fp32)
    mma_gemm<2><<<gD, 256, GEMM_SMEM>>>(TOK, D_MODEL, D_MODEL,
        att_hi, att_lo, wo_hi, wo_lo, x, x1, nullptr, nullptr);

    // 5) rmsnorm(x1) -> h (bf16 hi/lo)
    rmsnorm_split<<<TOK, 256>>>(x1, w_norm_mlp, h_hi, h_lo);

    // 6) up projection + gelu (split-store)
    dim3 gU(MLP_DIM / 256, TOK / 128);
    mma_gemm<1><<<gU, 256, GEMM_SMEM>>>(TOK, MLP_DIM, D_MODEL,
        h_hi, h_lo, wu_hi, wu_lo, nullptr, nullptr, up_hi, up_lo);

    // 7) down projection + residual -> out (fp32)
    mma_gemm<2><<<gD, 256, GEMM_SMEM>>>(TOK, D_MODEL, MLP_DIM,
        up_hi, up_lo, wd_hi, wd_lo, x1, out, nullptr, nullptr);
}